// round 6
// baseline (speedup 1.0000x reference)
#include <cuda_runtime.h>
#include <mma.h>

using namespace nvcuda;

// ---------------------------------------------------------------------------
// Attention_50921132261730 — R6: 256-thread DB GEMMs + fused bias
//   qkv = Wqkv @ x            (tf32 WMMA, double-buffered, 8 warps)
//   q,k <- l2norm * scales (SCALE folded into q), in place
//   flash: tf32 WMMA, 2x2 warp split (unchanged from R5)
//   out = Wout @ ao + bout    (tf32 WMMA, DB, bias in accumulator init)
// ---------------------------------------------------------------------------

constexpr int Bb = 2, Cc = 512, Nn = 2048, HEADS = 16, DHEAD = 64;
constexpr int HDIM = HEADS * DHEAD;    // 1024

__device__ float g_qkv[(long)Bb * 3 * HDIM * Nn];
__device__ float g_ao [(long)Bb * HDIM * Nn];

__device__ __forceinline__ float t32(float x) { return wmma::__float_to_tf32(x); }

// ---------------------------------------------------------------------------
// Double-buffered tf32 WMMA GEMM, 256 threads: C[z] = A @ B[z] (+ bias[m])
//   A [M,K] row-major (weights), B [K,Nn] row-major per batch z.
// ---------------------------------------------------------------------------
template<int BM,int BN,int WM,int WN,bool BIAS>
__global__ void __launch_bounds__(256)
wgemm3(const float* __restrict__ Ag, const float* __restrict__ Bg,
       float* __restrict__ Cg, const float* __restrict__ bias,
       int K, long sB, long sC)
{
    constexpr int NT = 256, BK = 16, LDA = BM + 4, LDB = BN + 4;
    constexpr int NWN = BN / WN;
    constexpr int AF4 = BM * BK / (4 * NT);
    constexpr int BF4 = BK * BN / (4 * NT);
    __shared__ float As[2][BK * LDA];
    __shared__ float Bs[2][BK * LDB];

    const float* B = Bg + (long)blockIdx.z * sB;
    float*       C = Cg + (long)blockIdx.z * sC;
    const int tid = threadIdx.x, wid = tid >> 5;
    const int m0 = blockIdx.y * BM, n0 = blockIdx.x * BN;
    const int wm = (wid / NWN) * WM, wn = (wid % NWN) * WN;

    wmma::fragment<wmma::accumulator,16,16,8,float> acc[WM/16][WN/16];

    if constexpr (BIAS) {
        // Stage bias[m] broadcast tile in As[0] space, load into accumulators.
        float* biasS = &As[0][0];                 // BM x 20
        for (int l = tid; l < BM * 20; l += NT)
            biasS[l] = bias[m0 + l / 20];
        __syncthreads();
        #pragma unroll
        for (int i = 0; i < WM/16; i++) {
            #pragma unroll
            for (int j = 0; j < WN/16; j++)
                wmma::load_matrix_sync(acc[i][j], biasS + (wm + i*16)*20, 20,
                                       wmma::mem_row_major);
        }
        __syncthreads();
    } else {
        #pragma unroll
        for (int i = 0; i < WM/16; i++)
            #pragma unroll
            for (int j = 0; j < WN/16; j++) wmma::fill_fragment(acc[i][j], 0.f);
    }

    float4 ra[AF4], rb[BF4];

    auto ldg = [&](int k0) {
        #pragma unroll
        for (int a = 0; a < AF4; a++) {
            int idx = tid + a*NT, mm = idx / (BK/4), kq = idx % (BK/4);
            ra[a] = *(const float4*)(Ag + (long)(m0+mm)*K + k0 + kq*4);
        }
        #pragma unroll
        for (int bi = 0; bi < BF4; bi++) {
            int idx = tid + bi*NT, kk = idx / (BN/4), nq = idx % (BN/4);
            rb[bi] = *(const float4*)(B + (long)(k0+kk)*Nn + n0 + nq*4);
        }
    };
    auto sts = [&](int buf) {
        #pragma unroll
        for (int a = 0; a < AF4; a++) {
            int idx = tid + a*NT, mm = idx / (BK/4), kq = idx % (BK/4);
            As[buf][(kq*4+0)*LDA + mm] = t32(ra[a].x);
            As[buf][(kq*4+1)*LDA + mm] = t32(ra[a].y);
            As[buf][(kq*4+2)*LDA + mm] = t32(ra[a].z);
            As[buf][(kq*4+3)*LDA + mm] = t32(ra[a].w);
        }
        #pragma unroll
        for (int bi = 0; bi < BF4; bi++) {
            int idx = tid + bi*NT, kk = idx / (BN/4), nq = idx % (BN/4);
            *(float4*)&Bs[buf][kk*LDB + nq*4] =
                make_float4(t32(rb[bi].x), t32(rb[bi].y), t32(rb[bi].z), t32(rb[bi].w));
        }
    };

    const int nI = K / BK;
    ldg(0);
    sts(0);
    __syncthreads();

    for (int it = 0; it < nI; it++) {
        const int cur = it & 1;
        if (it + 1 < nI) ldg((it + 1) * BK);

        #pragma unroll
        for (int kc = 0; kc < BK; kc += 8) {
            wmma::fragment<wmma::matrix_a,16,16,8,wmma::precision::tf32,wmma::col_major> af[WM/16];
            #pragma unroll
            for (int i = 0; i < WM/16; i++)
                wmma::load_matrix_sync(af[i], &As[cur][kc*LDA + wm + i*16], LDA);
            #pragma unroll
            for (int j = 0; j < WN/16; j++) {
                wmma::fragment<wmma::matrix_b,16,16,8,wmma::precision::tf32,wmma::row_major> bf;
                wmma::load_matrix_sync(bf, &Bs[cur][kc*LDB + wn + j*16], LDB);
                #pragma unroll
                for (int i = 0; i < WM/16; i++)
                    wmma::mma_sync(acc[i][j], af[i], bf, acc[i][j]);
            }
        }

        if (it + 1 < nI) sts(cur ^ 1);
        __syncthreads();
    }

    #pragma unroll
    for (int i = 0; i < WM/16; i++)
        #pragma unroll
        for (int j = 0; j < WN/16; j++)
            wmma::store_matrix_sync(C + (long)(m0+wm+i*16)*Nn + n0 + wn + j*16,
                                    acc[i][j], Nn, wmma::mem_row_major);
}

// ---------------------------------------------------------------------------
// Fused l2-normalize over head-dim + per-dim scales, in place on q,k regions.
// ---------------------------------------------------------------------------
__global__ void norm_scale_k(float* __restrict__ qkv,
                             const float* __restrict__ q_scale,
                             const float* __restrict__ k_scale)
{
    int gid = blockIdx.x * blockDim.x + threadIdx.x;
    int n   = gid & (Nn - 1);
    int h   = (gid >> 11) & (HEADS - 1);
    int sel = (gid >> 15) & 1;
    int b   = gid >> 16;

    float* p = qkv + ((long)b * 3 * HDIM + sel * HDIM + h * DHEAD) * Nn + n;
    float v[DHEAD];
    float ss = 0.f;
    #pragma unroll
    for (int d = 0; d < DHEAD; d++) {
        v[d] = p[(long)d * Nn];
        ss += v[d] * v[d];
    }
    float nrm = fmaxf(sqrtf(ss), 1e-12f);
    float inv = (sel ? 1.0f : 8.0f) / nrm;
    const float* sc = sel ? k_scale : q_scale;
    #pragma unroll
    for (int d = 0; d < DHEAD; d++)
        p[(long)d * Nn] = v[d] * inv * sc[d];
}

// ---------------------------------------------------------------------------
// Flash attention, tf32 WMMA, 2x2 warp split (unchanged from R5).
// ---------------------------------------------------------------------------
constexpr int FLD  = 132;   // 128 + 4
constexpr int SLD  = 68;    // 64 + 4
constexpr int KS_OFF = 0;
constexpr int VS_OFF = 64*FLD;
constexpr int SS_OFF = 2*64*FLD;
constexpr int RS_OFF = SS_OFF + 4*32*SLD;
constexpr int FLASH_SMEM = (RS_OFF + 128) * 4; // 102,912 B

__global__ void __launch_bounds__(128, 2)
flash2(const float* __restrict__ qkv, float* __restrict__ ao)
{
    extern __shared__ float sm[];
    float* Ks  = sm + KS_OFF;
    float* Vs  = sm + VS_OFF;
    float* Ssb = sm + SS_OFF;
    float* rs  = sm + RS_OFF;

    const int tid = threadIdx.x, wid = tid >> 5, lane = tid & 31;
    const int r = wid >> 1, c = wid & 1;
    const int qi0 = blockIdx.x * 64;
    const int bh = blockIdx.y;
    const int b = bh >> 4, h = bh & 15;

    const float* qg = qkv + ((long)b*3*HDIM + h*DHEAD)*Nn;
    const float* kg = qg + (long)HDIM*Nn;
    const float* vg = qg + (long)2*HDIM*Nn;

    for (int l = tid; l < 64*16; l += 128) {
        int d = l >> 4, i4 = (l & 15) * 4;
        float4 v = *(const float4*)(qg + (long)d*Nn + qi0 + i4);
        *(float4*)(Ssb + d*SLD + i4) =
            make_float4(t32(v.x), t32(v.y), t32(v.z), t32(v.w));
    }
    __syncthreads();

    wmma::fragment<wmma::matrix_a,16,16,8,wmma::precision::tf32,wmma::col_major> qf[2][8];
    #pragma unroll
    for (int m = 0; m < 2; m++)
        #pragma unroll
        for (int dc = 0; dc < 8; dc++)
            wmma::load_matrix_sync(qf[m][dc], Ssb + dc*8*SLD + r*32 + m*16, SLD);

    wmma::fragment<wmma::accumulator,16,16,8,float> of[2][4];
    #pragma unroll
    for (int m = 0; m < 2; m++)
        #pragma unroll
        for (int dt = 0; dt < 4; dt++) wmma::fill_fragment(of[m][dt], 0.f);

    float rowsum = 0.f;
    float* Sw = Ssb + wid * (32*SLD);
    __syncthreads();

    for (int kt = 0; kt < Nn; kt += 128) {
        for (int l = tid; l < 64*32; l += 128) {
            int d = l >> 5, j4 = (l & 31) * 4;
            float4 v = *(const float4*)(kg + (long)d*Nn + kt + j4);
            *(float4*)(Ks + d*FLD + j4) =
                make_float4(t32(v.x), t32(v.y), t32(v.z), t32(v.w));
            float4 w = *(const float4*)(vg + (long)d*Nn + kt + j4);
            *(float4*)(Vs + d*FLD + j4) =
                make_float4(t32(w.x), t32(w.y), t32(w.z), t32(w.w));
        }
        __syncthreads();

        wmma::fragment<wmma::accumulator,16,16,8,float> sf[2][4];
        #pragma unroll
        for (int m = 0; m < 2; m++)
            #pragma unroll
            for (int j = 0; j < 4; j++) wmma::fill_fragment(sf[m][j], 0.f);
        #pragma unroll
        for (int dc = 0; dc < 8; dc++) {
            #pragma unroll
            for (int j = 0; j < 4; j++) {
                wmma::fragment<wmma::matrix_b,16,16,8,wmma::precision::tf32,wmma::row_major> bf;
                wmma::load_matrix_sync(bf, Ks + dc*8*FLD + c*64 + j*16, FLD);
                wmma::mma_sync(sf[0][j], qf[0][dc], bf, sf[0][j]);
                wmma::mma_sync(sf[1][j], qf[1][dc], bf, sf[1][j]);
            }
        }
        #pragma unroll
        for (int m = 0; m < 2; m++)
            #pragma unroll
            for (int j = 0; j < 4; j++)
                wmma::store_matrix_sync(Sw + m*16*SLD + j*16, sf[m][j], SLD,
                                        wmma::mem_row_major);
        __syncwarp();

        {
            float4* p = (float4*)(Sw + lane*SLD);
            float s = 0.f;
            #pragma unroll
            for (int g = 0; g < 16; g++) {
                float4 v = p[g];
                v.x = __expf(v.x); v.y = __expf(v.y);
                v.z = __expf(v.z); v.w = __expf(v.w);
                s += v.x + v.y + v.z + v.w;
                p[g] = make_float4(t32(v.x), t32(v.y), t32(v.z), t32(v.w));
            }
            rowsum += s;
        }
        __syncwarp();

        #pragma unroll
        for (int j0 = 0; j0 < 8; j0++) {
            wmma::fragment<wmma::matrix_a,16,16,8,wmma::precision::tf32,wmma::row_major> af[2];
            #pragma unroll
            for (int m = 0; m < 2; m++)
                wmma::load_matrix_sync(af[m], Sw + m*16*SLD + j0*8, SLD);
            #pragma unroll
            for (int dt = 0; dt < 4; dt++) {
                wmma::fragment<wmma::matrix_b,16,16,8,wmma::precision::tf32,wmma::col_major> bf;
                wmma::load_matrix_sync(bf, Vs + dt*16*FLD + c*64 + j0*8, FLD);
                wmma::mma_sync(of[0][dt], af[0], bf, of[0][dt]);
                wmma::mma_sync(of[1][dt], af[1], bf, of[1][dt]);
            }
        }
        __syncthreads();
    }

    #pragma unroll
    for (int m = 0; m < 2; m++)
        #pragma unroll
        for (int dt = 0; dt < 4; dt++)
            wmma::store_matrix_sync(Sw + m*16*SLD + dt*16, of[m][dt], SLD,
                                    wmma::mem_row_major);
    rs[wid*32 + lane] = rowsum;
    __syncthreads();

    {
        const int i = tid & 63, db = (tid >> 6) * 32;
        const int wA = (i >> 5) * 2, il = i & 31;
        float inv = 1.0f / (rs[wA*32 + il] + rs[(wA+1)*32 + il]);
        const float* SA = Ssb + wA*(32*SLD) + il*SLD;
        const float* SB = SA + 32*SLD;
        float* aog = ao + ((long)b*HDIM + h*DHEAD)*Nn + qi0 + i;
        #pragma unroll
        for (int d = 0; d < 32; d++) {
            int dd = db + d;
            aog[(long)dd*Nn] = (SA[dd] + SB[dd]) * inv;
        }
    }
}

// ---------------------------------------------------------------------------
extern "C" void kernel_launch(void* const* d_in, const int* in_sizes, int n_in,
                              void* d_out, int out_size)
{
    (void)in_sizes; (void)n_in; (void)out_size;
    const float* x       = (const float*)d_in[0];
    const float* Wqkv    = (const float*)d_in[1];
    const float* q_scale = (const float*)d_in[2];
    const float* k_scale = (const float*)d_in[3];
    const float* Wout    = (const float*)d_in[4];
    const float* bout    = (const float*)d_in[5];
    float* out = (float*)d_out;

    float *qkv, *ao;
    cudaGetSymbolAddress((void**)&qkv, g_qkv);
    cudaGetSymbolAddress((void**)&ao,  g_ao);

    cudaFuncSetAttribute(flash2, cudaFuncAttributeMaxDynamicSharedMemorySize,
                         FLASH_SMEM);

    // 1) qkv = Wqkv @ x   (M=3072, K=512)
    wgemm3<128,128,64,32,false><<<dim3(Nn/128, 3072/128, Bb), 256>>>(
        Wqkv, x, qkv, nullptr, Cc, (long)Cc*Nn, (long)3*HDIM*Nn);

    // 2) l2-normalize q,k (+scales, SCALE folded into q)
    norm_scale_k<<<(Bb*2*HEADS*Nn)/256, 256>>>(qkv, q_scale, k_scale);

    // 3) flash attention -> ao (channel-major)
    flash2<<<dim3(Nn/64, Bb*HEADS), 128, FLASH_SMEM>>>(qkv, ao);

    // 4) out = Wout @ ao + bout   (M=512, K=1024, bias fused)
    wgemm3<64,128,32,32,true><<<dim3(Nn/128, Cc/64, Bb), 256>>>(
        Wout, ao, out, bout, HDIM, (long)HDIM*Nn, (long)Cc*Nn);
}

// round 7
// speedup vs baseline: 2.3302x; 2.3302x over previous
#include <cuda_runtime.h>
#include <cuda_fp16.h>
#include <mma.h>

using namespace nvcuda;

// ---------------------------------------------------------------------------
// Attention_50921132261730 — R7: all-fp16 mma.sync pipeline (2x tf32 rate,
// same 10-bit mantissa => same precision as tf32 path)
//   qkv = Wqkv @ x            (fp16 WMMA m16n16k16, fp32 accum, DB)
//   q,k <- l2norm * scales (SCALE folded into q), in place (fp32)
//   flash: fp16 WMMA, 2x2 warp split, fp32 S/exp, fp16 P, no max-shift
//   out = Wout @ ao + bout    (fp16 WMMA, bias in accumulator init)
// ---------------------------------------------------------------------------

constexpr int Bb = 2, Cc = 512, Nn = 2048, HEADS = 16, DHEAD = 64;
constexpr int HDIM = HEADS * DHEAD;    // 1024

__device__ float g_qkv[(long)Bb * 3 * HDIM * Nn];
__device__ float g_ao [(long)Bb * HDIM * Nn];

__device__ __forceinline__ uint2 pack4h(float4 v) {
    half2 a = __floats2half2_rn(v.x, v.y);
    half2 b = __floats2half2_rn(v.z, v.w);
    uint2 r;
    r.x = *reinterpret_cast<unsigned*>(&a);
    r.y = *reinterpret_cast<unsigned*>(&b);
    return r;
}

// ---------------------------------------------------------------------------
// Double-buffered fp16 WMMA GEMM, 256 threads: C[z] = A @ B[z] (+ bias[m])
//   A [M,K] row-major (weights), B [K,Nn] row-major per batch z.
// ---------------------------------------------------------------------------
template<int BM,int BN,int WM,int WN,bool BIAS>
__global__ void __launch_bounds__(256)
hgemm(const float* __restrict__ Ag, const float* __restrict__ Bg,
      float* __restrict__ Cg, const float* __restrict__ bias,
      int K, long sB, long sC)
{
    constexpr int NT = 256, BK = 32, LDA = BM + 8, LDB = BN + 8;
    constexpr int NWN = BN / WN;
    constexpr int AF4 = BM * BK / (4 * NT);
    constexpr int BF4 = BK * BN / (4 * NT);
    __shared__ half As[2][BK * LDA];
    __shared__ half Bs[2][BK * LDB];

    const float* B = Bg + (long)blockIdx.z * sB;
    float*       C = Cg + (long)blockIdx.z * sC;
    const int tid = threadIdx.x, wid = tid >> 5;
    const int m0 = blockIdx.y * BM, n0 = blockIdx.x * BN;
    const int wm = (wid / NWN) * WM, wn = (wid % NWN) * WN;

    wmma::fragment<wmma::accumulator,16,16,16,float> acc[WM/16][WN/16];

    if constexpr (BIAS) {
        float* biasS = (float*)&As[0][0];          // BM x 20 floats
        for (int l = tid; l < BM * 20; l += NT)
            biasS[l] = bias[m0 + l / 20];
        __syncthreads();
        #pragma unroll
        for (int i = 0; i < WM/16; i++)
            #pragma unroll
            for (int j = 0; j < WN/16; j++)
                wmma::load_matrix_sync(acc[i][j], biasS + (wm + i*16)*20, 20,
                                       wmma::mem_row_major);
        __syncthreads();
    } else {
        #pragma unroll
        for (int i = 0; i < WM/16; i++)
            #pragma unroll
            for (int j = 0; j < WN/16; j++) wmma::fill_fragment(acc[i][j], 0.f);
    }

    float4 ra[AF4], rb[BF4];

    auto ldg = [&](int k0) {
        #pragma unroll
        for (int a = 0; a < AF4; a++) {
            int idx = tid + a*NT, mm = idx / (BK/4), kq = idx % (BK/4);
            ra[a] = *(const float4*)(Ag + (long)(m0+mm)*K + k0 + kq*4);
        }
        #pragma unroll
        for (int bi = 0; bi < BF4; bi++) {
            int idx = tid + bi*NT, kk = idx / (BN/4), nq = idx % (BN/4);
            rb[bi] = *(const float4*)(B + (long)(k0+kk)*Nn + n0 + nq*4);
        }
    };
    auto sts = [&](int buf) {
        #pragma unroll
        for (int a = 0; a < AF4; a++) {
            int idx = tid + a*NT, mm = idx / (BK/4), kq = idx % (BK/4);
            As[buf][(kq*4+0)*LDA + mm] = __float2half_rn(ra[a].x);
            As[buf][(kq*4+1)*LDA + mm] = __float2half_rn(ra[a].y);
            As[buf][(kq*4+2)*LDA + mm] = __float2half_rn(ra[a].z);
            As[buf][(kq*4+3)*LDA + mm] = __float2half_rn(ra[a].w);
        }
        #pragma unroll
        for (int bi = 0; bi < BF4; bi++) {
            int idx = tid + bi*NT, kk = idx / (BN/4), nq = idx % (BN/4);
            *(uint2*)&Bs[buf][kk*LDB + nq*4] = pack4h(rb[bi]);
        }
    };

    const int nI = K / BK;
    ldg(0);
    sts(0);
    __syncthreads();

    for (int it = 0; it < nI; it++) {
        const int cur = it & 1;
        if (it + 1 < nI) ldg((it + 1) * BK);

        #pragma unroll
        for (int kc = 0; kc < BK; kc += 16) {
            wmma::fragment<wmma::matrix_a,16,16,16,half,wmma::col_major> af[WM/16];
            #pragma unroll
            for (int i = 0; i < WM/16; i++)
                wmma::load_matrix_sync(af[i], &As[cur][kc*LDA + wm + i*16], LDA);
            #pragma unroll
            for (int j = 0; j < WN/16; j++) {
                wmma::fragment<wmma::matrix_b,16,16,16,half,wmma::row_major> bf;
                wmma::load_matrix_sync(bf, &Bs[cur][kc*LDB + wn + j*16], LDB);
                #pragma unroll
                for (int i = 0; i < WM/16; i++)
                    wmma::mma_sync(acc[i][j], af[i], bf, acc[i][j]);
            }
        }

        if (it + 1 < nI) sts(cur ^ 1);
        __syncthreads();
    }

    #pragma unroll
    for (int i = 0; i < WM/16; i++)
        #pragma unroll
        for (int j = 0; j < WN/16; j++)
            wmma::store_matrix_sync(C + (long)(m0+wm+i*16)*Nn + n0 + wn + j*16,
                                    acc[i][j], Nn, wmma::mem_row_major);
}

// ---------------------------------------------------------------------------
// Fused l2-normalize over head-dim + per-dim scales, in place on q,k regions.
// ---------------------------------------------------------------------------
__global__ void norm_scale_k(float* __restrict__ qkv,
                             const float* __restrict__ q_scale,
                             const float* __restrict__ k_scale)
{
    int gid = blockIdx.x * blockDim.x + threadIdx.x;
    int n   = gid & (Nn - 1);
    int h   = (gid >> 11) & (HEADS - 1);
    int sel = (gid >> 15) & 1;
    int b   = gid >> 16;

    float* p = qkv + ((long)b * 3 * HDIM + sel * HDIM + h * DHEAD) * Nn + n;
    float v[DHEAD];
    float ss = 0.f;
    #pragma unroll
    for (int d = 0; d < DHEAD; d++) {
        v[d] = p[(long)d * Nn];
        ss += v[d] * v[d];
    }
    float nrm = fmaxf(sqrtf(ss), 1e-12f);
    float inv = (sel ? 1.0f : 8.0f) / nrm;
    const float* sc = sel ? k_scale : q_scale;
    #pragma unroll
    for (int d = 0; d < DHEAD; d++)
        p[(long)d * Nn] = v[d] * inv * sc[d];
}

// ---------------------------------------------------------------------------
// Flash attention, fp16 WMMA m16n16k16, 2x2 warp split.
// CTA: 64 q-rows, 128 threads. Warp (r,c): S rows r*32..+32, cols c*64..+64.
// Q frags in regs; S accum fp32 -> exp fp32 -> P fp16; no max-shift (|S|<=8).
// ---------------------------------------------------------------------------
constexpr int FLH  = 136;  // K/V half ld (128+8)
constexpr int QLH  = 72;   // Q stage half ld (64+8)
constexpr int PLH  = 72;   // P half ld
constexpr int SLDf = 68;   // S float ld (64+4)
// byte offsets in dynamic smem
constexpr int KS_B = 0;                         // 64*136*2 = 17408
constexpr int VS_B = 17408;                     // 17408
constexpr int SF_B = 34816;                     // 4*32*68*4 = 34816 (also Q stage)
constexpr int PH_B = 69632;                     // 4*32*72*2 = 18432
constexpr int RS_B = 88064;                     // 128*4
constexpr int FLASH_SMEM = 88576;

__global__ void __launch_bounds__(128, 2)
flash_h(const float* __restrict__ qkv, float* __restrict__ ao)
{
    extern __shared__ char smc[];
    half*  Ks = (half*)(smc + KS_B);
    half*  Vs = (half*)(smc + VS_B);
    float* Sf = (float*)(smc + SF_B);
    half*  Ph = (half*)(smc + PH_B);
    float* rs = (float*)(smc + RS_B);
    half*  Qst = (half*)(smc + SF_B);   // Q staged in Sf region

    const int tid = threadIdx.x, wid = tid >> 5, lane = tid & 31;
    const int r = wid >> 1, c = wid & 1;
    const int qi0 = blockIdx.x * 64;
    const int bh = blockIdx.y;
    const int b = bh >> 4, h = bh & 15;

    const float* qg = qkv + ((long)b*3*HDIM + h*DHEAD)*Nn;
    const float* kg = qg + (long)HDIM*Nn;
    const float* vg = qg + (long)2*HDIM*Nn;

    // ---- Q stage (d,i) 64x64 half ----
    for (int l = tid; l < 64*16; l += 128) {
        int d = l >> 4, i4 = (l & 15) * 4;
        float4 v = *(const float4*)(qg + (long)d*Nn + qi0 + i4);
        *(uint2*)&Qst[d*QLH + i4] = pack4h(v);
    }
    __syncthreads();

    // ---- Q frags: warp's 32 rows x 4 k-chunks of 16 ----
    wmma::fragment<wmma::matrix_a,16,16,16,half,wmma::col_major> qf[2][4];
    #pragma unroll
    for (int m = 0; m < 2; m++)
        #pragma unroll
        for (int kc = 0; kc < 4; kc++)
            wmma::load_matrix_sync(qf[m][kc], Qst + kc*16*QLH + r*32 + m*16, QLH);

    wmma::fragment<wmma::accumulator,16,16,16,float> of[2][4];
    #pragma unroll
    for (int m = 0; m < 2; m++)
        #pragma unroll
        for (int dt = 0; dt < 4; dt++) wmma::fill_fragment(of[m][dt], 0.f);

    float rowsum = 0.f;
    float* Sw  = Sf + wid * (32*SLDf);
    half*  Phw = Ph + wid * (32*PLH);
    __syncthreads();   // qf loads done before Sf reused as S

    for (int kt = 0; kt < Nn; kt += 128) {
        // ---- fill K,V tiles (half) ----
        for (int l = tid; l < 64*32; l += 128) {
            int d = l >> 5, j4 = (l & 31) * 4;
            float4 v = *(const float4*)(kg + (long)d*Nn + kt + j4);
            *(uint2*)&Ks[d*FLH + j4] = pack4h(v);
            float4 w = *(const float4*)(vg + (long)d*Nn + kt + j4);
            *(uint2*)&Vs[d*FLH + j4] = pack4h(w);
        }
        __syncthreads();

        // ---- S = Q^T K : warp 32 rows x 64-col slice, fp32 accum ----
        wmma::fragment<wmma::accumulator,16,16,16,float> sf[2][4];
        #pragma unroll
        for (int m = 0; m < 2; m++)
            #pragma unroll
            for (int j = 0; j < 4; j++) wmma::fill_fragment(sf[m][j], 0.f);
        #pragma unroll
        for (int kc = 0; kc < 4; kc++) {
            #pragma unroll
            for (int j = 0; j < 4; j++) {
                wmma::fragment<wmma::matrix_b,16,16,16,half,wmma::row_major> bf;
                wmma::load_matrix_sync(bf, Ks + kc*16*FLH + c*64 + j*16, FLH);
                wmma::mma_sync(sf[0][j], qf[0][kc], bf, sf[0][j]);
                wmma::mma_sync(sf[1][j], qf[1][kc], bf, sf[1][j]);
            }
        }
        #pragma unroll
        for (int m = 0; m < 2; m++)
            #pragma unroll
            for (int j = 0; j < 4; j++)
                wmma::store_matrix_sync(Sw + m*16*SLDf + j*16, sf[m][j], SLDf,
                                        wmma::mem_row_major);
        __syncwarp();

        // ---- P = exp(S) (no shift); per-thread rowsum; P -> fp16 ----
        {
            const float4* p = (const float4*)(Sw + lane*SLDf);
            uint4* dst = (uint4*)(Phw + lane*PLH);
            float s = 0.f;
            #pragma unroll
            for (int g = 0; g < 8; g++) {
                float4 a = p[2*g], bq = p[2*g+1];
                a.x = __expf(a.x); a.y = __expf(a.y);
                a.z = __expf(a.z); a.w = __expf(a.w);
                bq.x = __expf(bq.x); bq.y = __expf(bq.y);
                bq.z = __expf(bq.z); bq.w = __expf(bq.w);
                s += a.x + a.y + a.z + a.w + bq.x + bq.y + bq.z + bq.w;
                uint2 u0 = pack4h(a), u1 = pack4h(bq);
                dst[g] = make_uint4(u0.x, u0.y, u1.x, u1.y);
            }
            rowsum += s;
        }
        __syncwarp();

        // ---- O += P @ V^T over warp's 64-j slice ----
        #pragma unroll
        for (int kc = 0; kc < 4; kc++) {
            wmma::fragment<wmma::matrix_a,16,16,16,half,wmma::row_major> af[2];
            #pragma unroll
            for (int m = 0; m < 2; m++)
                wmma::load_matrix_sync(af[m], Phw + m*16*PLH + kc*16, PLH);
            #pragma unroll
            for (int dt = 0; dt < 4; dt++) {
                wmma::fragment<wmma::matrix_b,16,16,16,half,wmma::col_major> bf;
                wmma::load_matrix_sync(bf, Vs + dt*16*FLH + c*64 + kc*16, FLH);
                wmma::mma_sync(of[0][dt], af[0], bf, of[0][dt]);
                wmma::mma_sync(of[1][dt], af[1], bf, of[1][dt]);
            }
        }
        __syncthreads();   // all warps done with Ks/Vs before next fill
    }

    // ---- reduce partial O + rowsum across warp pair; write ao ----
    #pragma unroll
    for (int m = 0; m < 2; m++)
        #pragma unroll
        for (int dt = 0; dt < 4; dt++)
            wmma::store_matrix_sync(Sw + m*16*SLDf + dt*16, of[m][dt], SLDf,
                                    wmma::mem_row_major);
    rs[wid*32 + lane] = rowsum;
    __syncthreads();

    {
        const int i = tid & 63, db = (tid >> 6) * 32;
        const int wA = (i >> 5) * 2, il = i & 31;
        float inv = 1.0f / (rs[wA*32 + il] + rs[(wA+1)*32 + il]);
        const float* SA = Sf + wA*(32*SLDf) + il*SLDf;
        const float* SB = SA + 32*SLDf;
        float* aog = ao + ((long)b*HDIM + h*DHEAD)*Nn + qi0 + i;
        #pragma unroll
        for (int d = 0; d < 32; d++) {
            int dd = db + d;
            aog[(long)dd*Nn] = (SA[dd] + SB[dd]) * inv;
        }
    }
}

// ---------------------------------------------------------------------------
extern "C" void kernel_launch(void* const* d_in, const int* in_sizes, int n_in,
                              void* d_out, int out_size)
{
    (void)in_sizes; (void)n_in; (void)out_size;
    const float* x       = (const float*)d_in[0];
    const float* Wqkv    = (const float*)d_in[1];
    const float* q_scale = (const float*)d_in[2];
    const float* k_scale = (const float*)d_in[3];
    const float* Wout    = (const float*)d_in[4];
    const float* bout    = (const float*)d_in[5];
    float* out = (float*)d_out;

    float *qkv, *ao;
    cudaGetSymbolAddress((void**)&qkv, g_qkv);
    cudaGetSymbolAddress((void**)&ao,  g_ao);

    cudaFuncSetAttribute(flash_h, cudaFuncAttributeMaxDynamicSharedMemorySize,
                         FLASH_SMEM);

    // 1) qkv = Wqkv @ x   (M=3072, K=512)
    hgemm<128,128,64,32,false><<<dim3(Nn/128, 3072/128, Bb), 256>>>(
        Wqkv, x, qkv, nullptr, Cc, (long)Cc*Nn, (long)3*HDIM*Nn);

    // 2) l2-normalize q,k (+scales, SCALE folded into q)
    norm_scale_k<<<(Bb*2*HEADS*Nn)/256, 256>>>(qkv, q_scale, k_scale);

    // 3) flash attention -> ao (channel-major)
    flash_h<<<dim3(Nn/64, Bb*HEADS), 128, FLASH_SMEM>>>(qkv, ao);

    // 4) out = Wout @ ao + bout   (M=512, K=1024, bias fused)
    hgemm<64,128,32,32,true><<<dim3(Nn/128, Cc/64, Bb), 256>>>(
        Wout, ao, out, bout, HDIM, (long)HDIM*Nn, (long)Cc*Nn);
}

// round 8
// speedup vs baseline: 2.7372x; 1.1747x over previous
#include <cuda_runtime.h>
#include <cuda_fp16.h>
#include <mma.h>

using namespace nvcuda;

// ---------------------------------------------------------------------------
// Attention_50921132261730 — R8: single-conversion fp16 dataflow
//   f2h: Wqkv, x, Wout -> fp16 once
//   qkv = Wqkv @ x            (fp16-in/fp32-out WMMA, DB, no inner converts)
//   norm: l2norm q,k * scales (SCALE into q) -> fp16 buffers [bh][d][n]
//   v -> fp16
//   flash: all-half loads, P aliased into S smem, 3 CTA/SM, ao out fp16
//   out = Wout @ ao + bout    (fp16-in, bias in accum init, fp32 out)
// ---------------------------------------------------------------------------

constexpr int Bb = 2, Cc = 512, Nn = 2048, HEADS = 16, DHEAD = 64;
constexpr int HDIM = HEADS * DHEAD;    // 1024
constexpr int BH = Bb * HEADS;         // 32

__device__ float g_qkv [(long)Bb * 3 * HDIM * Nn];
__device__ half  g_Wqh [3 * HDIM * Cc];
__device__ half  g_xh  [(long)Bb * Cc * Nn];
__device__ half  g_Woh [Cc * HDIM];
__device__ half  g_qh  [(long)BH * DHEAD * Nn];
__device__ half  g_kh  [(long)BH * DHEAD * Nn];
__device__ half  g_vh  [(long)BH * DHEAD * Nn];
__device__ half  g_aoh [(long)Bb * HDIM * Nn];

__device__ __forceinline__ uint2 pack4h(float4 v) {
    half2 a = __floats2half2_rn(v.x, v.y);
    half2 b = __floats2half2_rn(v.z, v.w);
    uint2 r;
    r.x = *reinterpret_cast<unsigned*>(&a);
    r.y = *reinterpret_cast<unsigned*>(&b);
    return r;
}

// ---------------------------------------------------------------------------
// fp32 -> fp16 bulk convert, 8 elems/thread
// ---------------------------------------------------------------------------
__global__ void f2h_k(const float* __restrict__ src, half* __restrict__ dst)
{
    long i = ((long)blockIdx.x * 256 + threadIdx.x) * 8;
    float4 a = *(const float4*)(src + i);
    float4 b = *(const float4*)(src + i + 4);
    uint2 pa = pack4h(a), pb = pack4h(b);
    *(uint4*)(dst + i) = make_uint4(pa.x, pa.y, pb.x, pb.y);
}

// ---------------------------------------------------------------------------
// fp16-input double-buffered WMMA GEMM, 256 threads: C[z] = A @ B[z] (+bias)
//   A half [M,K] row-major, B half [K,Nn] per batch z, C float.
// ---------------------------------------------------------------------------
template<int BM,int BN,int WM,int WN,bool BIAS>
__global__ void __launch_bounds__(256)
hgemm2(const half* __restrict__ Ag, const half* __restrict__ Bg,
       float* __restrict__ Cg, const float* __restrict__ bias,
       int K, long sB, long sC)
{
    constexpr int NT = 256, BK = 32, LDA = BM + 8, LDB = BN + 8;
    constexpr int NWN = BN / WN;
    constexpr int AG = BM * (BK/8) / NT;   // uint4 groups for A
    constexpr int BG = BK * (BN/8) / NT;   // uint4 groups for B
    __shared__ half As[2][BK * LDA];
    __shared__ half Bs[2][BK * LDB];

    const half* B = Bg + (long)blockIdx.z * sB;
    float*      C = Cg + (long)blockIdx.z * sC;
    const int tid = threadIdx.x, wid = tid >> 5;
    const int m0 = blockIdx.y * BM, n0 = blockIdx.x * BN;
    const int wm = (wid / NWN) * WM, wn = (wid % NWN) * WN;

    wmma::fragment<wmma::accumulator,16,16,16,float> acc[WM/16][WN/16];

    if constexpr (BIAS) {
        float* biasS = (float*)&As[0][0];        // BM x 20 floats
        for (int l = tid; l < BM * 20; l += NT)
            biasS[l] = bias[m0 + l / 20];
        __syncthreads();
        #pragma unroll
        for (int i = 0; i < WM/16; i++)
            #pragma unroll
            for (int j = 0; j < WN/16; j++)
                wmma::load_matrix_sync(acc[i][j], biasS + (wm + i*16)*20, 20,
                                       wmma::mem_row_major);
        __syncthreads();
    } else {
        #pragma unroll
        for (int i = 0; i < WM/16; i++)
            #pragma unroll
            for (int j = 0; j < WN/16; j++) wmma::fill_fragment(acc[i][j], 0.f);
    }

    uint4 ua[AG], ub[BG];

    auto ldg = [&](int k0) {
        #pragma unroll
        for (int a = 0; a < AG; a++) {
            int idx = tid + a*NT, mm = idx / (BK/8), kq = idx % (BK/8);
            ua[a] = *(const uint4*)(Ag + (long)(m0+mm)*K + k0 + kq*8);
        }
        #pragma unroll
        for (int bi = 0; bi < BG; bi++) {
            int idx = tid + bi*NT, kk = idx / (BN/8), nq = idx % (BN/8);
            ub[bi] = *(const uint4*)(B + (long)(k0+kk)*Nn + n0 + nq*8);
        }
    };
    auto sts = [&](int buf) {
        #pragma unroll
        for (int a = 0; a < AG; a++) {
            int idx = tid + a*NT, mm = idx / (BK/8), kq = idx % (BK/8);
            half hb[8];
            *(uint4*)hb = ua[a];
            #pragma unroll
            for (int t = 0; t < 8; t++)
                As[buf][(kq*8+t)*LDA + mm] = hb[t];
        }
        #pragma unroll
        for (int bi = 0; bi < BG; bi++) {
            int idx = tid + bi*NT, kk = idx / (BN/8), nq = idx % (BN/8);
            *(uint4*)&Bs[buf][kk*LDB + nq*8] = ub[bi];
        }
    };

    const int nI = K / BK;
    ldg(0);
    sts(0);
    __syncthreads();

    for (int it = 0; it < nI; it++) {
        const int cur = it & 1;
        if (it + 1 < nI) ldg((it + 1) * BK);

        #pragma unroll
        for (int kc = 0; kc < BK; kc += 16) {
            wmma::fragment<wmma::matrix_a,16,16,16,half,wmma::col_major> af[WM/16];
            #pragma unroll
            for (int i = 0; i < WM/16; i++)
                wmma::load_matrix_sync(af[i], &As[cur][kc*LDA + wm + i*16], LDA);
            #pragma unroll
            for (int j = 0; j < WN/16; j++) {
                wmma::fragment<wmma::matrix_b,16,16,16,half,wmma::row_major> bf;
                wmma::load_matrix_sync(bf, &Bs[cur][kc*LDB + wn + j*16], LDB);
                #pragma unroll
                for (int i = 0; i < WM/16; i++)
                    wmma::mma_sync(acc[i][j], af[i], bf, acc[i][j]);
            }
        }

        if (it + 1 < nI) sts(cur ^ 1);
        __syncthreads();
    }

    #pragma unroll
    for (int i = 0; i < WM/16; i++)
        #pragma unroll
        for (int j = 0; j < WN/16; j++)
            wmma::store_matrix_sync(C + (long)(m0+wm+i*16)*Nn + n0 + wn + j*16,
                                    acc[i][j], Nn, wmma::mem_row_major);
}

// ---------------------------------------------------------------------------
// l2-normalize q,k (+scales, SCALE folded into q); fp32 in, fp16 out [bh][d][n]
// ---------------------------------------------------------------------------
__global__ void norm_scale_k(const float* __restrict__ qkv,
                             const float* __restrict__ q_scale,
                             const float* __restrict__ k_scale,
                             half* __restrict__ qh, half* __restrict__ kh)
{
    int gid = blockIdx.x * blockDim.x + threadIdx.x;
    int n   = gid & (Nn - 1);
    int h   = (gid >> 11) & (HEADS - 1);
    int sel = (gid >> 15) & 1;
    int b   = gid >> 16;

    const float* p = qkv + ((long)b * 3 * HDIM + sel * HDIM + h * DHEAD) * Nn + n;
    float v[DHEAD];
    float ss = 0.f;
    #pragma unroll
    for (int d = 0; d < DHEAD; d++) {
        v[d] = p[(long)d * Nn];
        ss += v[d] * v[d];
    }
    float nrm = fmaxf(sqrtf(ss), 1e-12f);
    float inv = (sel ? 1.0f : 8.0f) / nrm;
    const float* sc = sel ? k_scale : q_scale;
    half* dst = (sel ? kh : qh) + ((long)(b*HEADS + h) * DHEAD) * Nn + n;
    #pragma unroll
    for (int d = 0; d < DHEAD; d++)
        dst[(long)d * Nn] = __float2half_rn(v[d] * inv * sc[d]);
}

// ---------------------------------------------------------------------------
// v fp32 -> fp16, layout preserved ([b][ch][n] == [bh][d][n])
// ---------------------------------------------------------------------------
__global__ void v_half_k(const float* __restrict__ qkv, half* __restrict__ vh)
{
    long e = ((long)blockIdx.x * 256 + threadIdx.x) * 8;
    long per_b = (long)HDIM * Nn;
    int  b = (int)(e / per_b);
    long r = e - (long)b * per_b;
    const float* src = qkv + ((long)b*3*HDIM + 2*HDIM)*Nn + r;
    float4 a = *(const float4*)src;
    float4 c = *(const float4*)(src + 4);
    uint2 pa = pack4h(a), pb = pack4h(c);
    *(uint4*)(vh + e) = make_uint4(pa.x, pa.y, pb.x, pb.y);
}

// ---------------------------------------------------------------------------
// Flash attention, fp16 WMMA, 2x2 warp split, all-half global traffic,
// P aliased into S smem -> 70KB smem -> 3 CTAs/SM. ao out fp16.
// ---------------------------------------------------------------------------
constexpr int FLH  = 136;  // K/V half ld (128+8)
constexpr int QLH  = 72;   // Q stage half ld
constexpr int SLDf = 68;   // S float ld (64+4)
constexpr int PLH  = 136;  // P half ld (= 2*SLDf, aliased)
constexpr int KS_B = 0;                       // 64*136*2 = 17408
constexpr int VS_B = 17408;
constexpr int SF_B = 34816;                   // 4*32*68*4 = 34816 (S / Qstage / P alias / O)
constexpr int RS_B = 69632;                   // 128*4
constexpr int FLASH_SMEM = 70144;

__global__ void __launch_bounds__(128, 3)
flash_h(const half* __restrict__ qhg, const half* __restrict__ khg,
        const half* __restrict__ vhg, half* __restrict__ aoh)
{
    extern __shared__ char smc[];
    half*  Ks = (half*)(smc + KS_B);
    half*  Vs = (half*)(smc + VS_B);
    float* Sf = (float*)(smc + SF_B);
    float* rs = (float*)(smc + RS_B);
    half*  Qst = (half*)(smc + SF_B);

    const int tid = threadIdx.x, wid = tid >> 5, lane = tid & 31;
    const int r = wid >> 1, c = wid & 1;
    const int qi0 = blockIdx.x * 64;
    const int bh = blockIdx.y;
    const int b = bh >> 4, h = bh & 15;

    const half* qg = qhg + (long)bh * DHEAD * Nn;
    const half* kg = khg + (long)bh * DHEAD * Nn;
    const half* vg = vhg + (long)bh * DHEAD * Nn;

    // ---- Q stage (d,i) 64x64 half ----
    for (int l = tid; l < 64*8; l += 128) {
        int d = l >> 3, i8 = (l & 7) * 8;
        *(uint4*)&Qst[d*QLH + i8] = *(const uint4*)(qg + (long)d*Nn + qi0 + i8);
    }
    __syncthreads();

    wmma::fragment<wmma::matrix_a,16,16,16,half,wmma::col_major> qf[2][4];
    #pragma unroll
    for (int m = 0; m < 2; m++)
        #pragma unroll
        for (int kc = 0; kc < 4; kc++)
            wmma::load_matrix_sync(qf[m][kc], Qst + kc*16*QLH + r*32 + m*16, QLH);

    wmma::fragment<wmma::accumulator,16,16,16,float> of[2][4];
    #pragma unroll
    for (int m = 0; m < 2; m++)
        #pragma unroll
        for (int dt = 0; dt < 4; dt++) wmma::fill_fragment(of[m][dt], 0.f);

    float rowsum = 0.f;
    float* Sw  = Sf + wid * (32*SLDf);
    half*  Phw = (half*)Sw;
    __syncthreads();   // qf loads done before Sf reused

    for (int kt = 0; kt < Nn; kt += 128) {
        // ---- fill K,V tiles (raw half copies) ----
        for (int l = tid; l < 64*16; l += 128) {
            int d = l >> 4, j8 = (l & 15) * 8;
            *(uint4*)&Ks[d*FLH + j8] = *(const uint4*)(kg + (long)d*Nn + kt + j8);
            *(uint4*)&Vs[d*FLH + j8] = *(const uint4*)(vg + (long)d*Nn + kt + j8);
        }
        __syncthreads();

        // ---- S = Q^T K : two j-groups to bound live registers ----
        #pragma unroll
        for (int jg = 0; jg < 2; jg++) {
            wmma::fragment<wmma::accumulator,16,16,16,float> sf[2][2];
            #pragma unroll
            for (int m = 0; m < 2; m++)
                #pragma unroll
                for (int jj = 0; jj < 2; jj++) wmma::fill_fragment(sf[m][jj], 0.f);
            #pragma unroll
            for (int kc = 0; kc < 4; kc++) {
                #pragma unroll
                for (int jj = 0; jj < 2; jj++) {
                    wmma::fragment<wmma::matrix_b,16,16,16,half,wmma::row_major> bf;
                    wmma::load_matrix_sync(bf, Ks + kc*16*FLH + c*64 + (jg*2+jj)*16, FLH);
                    wmma::mma_sync(sf[0][jj], qf[0][kc], bf, sf[0][jj]);
                    wmma::mma_sync(sf[1][jj], qf[1][kc], bf, sf[1][jj]);
                }
            }
            #pragma unroll
            for (int m = 0; m < 2; m++)
                #pragma unroll
                for (int jj = 0; jj < 2; jj++)
                    wmma::store_matrix_sync(Sw + m*16*SLDf + (jg*2+jj)*16,
                                            sf[m][jj], SLDf, wmma::mem_row_major);
        }
        __syncwarp();

        // ---- P = exp(S) (no shift, |S|<=8); fp16 P written over S rows ----
        {
            float* prow = Sw + lane*SLDf;
            half*  drow = (half*)prow;
            float s = 0.f;
            // phase 0: floats 0..31 -> halves 0..31 (float slots 0..15)
            {
                float4 t[8];
                #pragma unroll
                for (int g = 0; g < 8; g++) {
                    float4 v = ((const float4*)prow)[g];
                    v.x = __expf(v.x); v.y = __expf(v.y);
                    v.z = __expf(v.z); v.w = __expf(v.w);
                    s += v.x + v.y + v.z + v.w;
                    t[g] = v;
                }
                #pragma unroll
                for (int g = 0; g < 4; g++) {
                    uint2 a = pack4h(t[2*g]), bq = pack4h(t[2*g+1]);
                    ((uint4*)drow)[g] = make_uint4(a.x, a.y, bq.x, bq.y);
                }
            }
            // phase 1: floats 32..63 -> halves 32..63 (float slots 16..31)
            {
                float4 t[8];
                #pragma unroll
                for (int g = 0; g < 8; g++) {
                    float4 v = ((const float4*)prow)[8+g];
                    v.x = __expf(v.x); v.y = __expf(v.y);
                    v.z = __expf(v.z); v.w = __expf(v.w);
                    s += v.x + v.y + v.z + v.w;
                    t[g] = v;
                }
                #pragma unroll
                for (int g = 0; g < 4; g++) {
                    uint2 a = pack4h(t[2*g]), bq = pack4h(t[2*g+1]);
                    ((uint4*)drow)[4+g] = make_uint4(a.x, a.y, bq.x, bq.y);
                }
            }
            rowsum += s;
        }
        __syncwarp();

        // ---- O += P @ V^T over warp's 64-j slice ----
        #pragma unroll
        for (int kc = 0; kc < 4; kc++) {
            wmma::fragment<wmma::matrix_a,16,16,16,half,wmma::row_major> af[2];
            #pragma unroll
            for (int m = 0; m < 2; m++)
                wmma::load_matrix_sync(af[m], Phw + m*16*PLH + kc*16, PLH);
            #pragma unroll
            for (int dt = 0; dt < 4; dt++) {
                wmma::fragment<wmma::matrix_b,16,16,16,half,wmma::col_major> bf;
                wmma::load_matrix_sync(bf, Vs + dt*16*FLH + c*64 + kc*16, FLH);
                wmma::mma_sync(of[0][dt], af[0], bf, of[0][dt]);
                wmma::mma_sync(of[1][dt], af[1], bf, of[1][dt]);
            }
        }
        __syncthreads();   // all warps done with Ks/Vs before next fill
    }

    // ---- reduce O + rowsum across warp pair; write aoh fp16 ----
    #pragma unroll
    for (int m = 0; m < 2; m++)
        #pragma unroll
        for (int dt = 0; dt < 4; dt++)
            wmma::store_matrix_sync(Sw + m*16*SLDf + dt*16, of[m][dt], SLDf,
                                    wmma::mem_row_major);
    rs[wid*32 + lane] = rowsum;
    __syncthreads();

    {
        const int i = tid & 63, db = (tid >> 6) * 32;
        const int wA = (i >> 5) * 2, il = i & 31;
        float inv = 1.0f / (rs[wA*32 + il] + rs[(wA+1)*32 + il]);
        const float* SA = Sf + wA*(32*SLDf) + il*SLDf;
        const float* SB = SA + 32*SLDf;
        half* aog = aoh + ((long)b*HDIM + h*DHEAD)*Nn + qi0 + i;
        #pragma unroll
        for (int d = 0; d < 32; d++) {
            int dd = db + d;
            aog[(long)dd*Nn] = __float2half_rn((SA[dd] + SB[dd]) * inv);
        }
    }
}

// ---------------------------------------------------------------------------
extern "C" void kernel_launch(void* const* d_in, const int* in_sizes, int n_in,
                              void* d_out, int out_size)
{
    (void)in_sizes; (void)n_in; (void)out_size;
    const float* x       = (const float*)d_in[0];
    const float* Wqkv    = (const float*)d_in[1];
    const float* q_scale = (const float*)d_in[2];
    const float* k_scale = (const float*)d_in[3];
    const float* Wout    = (const float*)d_in[4];
    const float* bout    = (const float*)d_in[5];
    float* out = (float*)d_out;

    float *qkv;
    half *Wqh, *xh, *Woh, *qh, *kh, *vh, *aoh;
    cudaGetSymbolAddress((void**)&qkv, g_qkv);
    cudaGetSymbolAddress((void**)&Wqh, g_Wqh);
    cudaGetSymbolAddress((void**)&xh,  g_xh);
    cudaGetSymbolAddress((void**)&Woh, g_Woh);
    cudaGetSymbolAddress((void**)&qh,  g_qh);
    cudaGetSymbolAddress((void**)&kh,  g_kh);
    cudaGetSymbolAddress((void**)&vh,  g_vh);
    cudaGetSymbolAddress((void**)&aoh, g_aoh);

    cudaFuncSetAttribute(flash_h, cudaFuncAttributeMaxDynamicSharedMemorySize,
                         FLASH_SMEM);

    // 0) one-time fp16 conversions
    f2h_k<<<(3*HDIM*Cc)/2048, 256>>>(Wqkv, Wqh);
    f2h_k<<<(int)(((long)Bb*Cc*Nn)/2048), 256>>>(x, xh);
    f2h_k<<<(Cc*HDIM)/2048, 256>>>(Wout, Woh);

    // 1) qkv = Wqkv @ x   (M=3072, K=512)
    hgemm2<128,128,64,32,false><<<dim3(Nn/128, 3072/128, Bb), 256>>>(
        Wqh, xh, qkv, nullptr, Cc, (long)Cc*Nn, (long)3*HDIM*Nn);

    // 2) l2-normalize q,k -> fp16 ; v -> fp16
    norm_scale_k<<<(Bb*2*HEADS*Nn)/256, 256>>>(qkv, q_scale, k_scale, qh, kh);
    v_half_k<<<(int)(((long)Bb*HDIM*Nn)/2048), 256>>>(qkv, vh);

    // 3) flash attention -> aoh (fp16, channel-major)
    flash_h<<<dim3(Nn/64, BH), 128, FLASH_SMEM>>>(qh, kh, vh, aoh);

    // 4) out = Wout @ ao + bout   (M=512, K=1024, bias fused)
    hgemm2<64,128,32,32,true><<<dim3(Nn/128, Cc/64, Bb), 256>>>(
        Woh, aoh, out, bout, HDIM, (long)HDIM*Nn, (long)Cc*Nn);
}

// round 9
// speedup vs baseline: 2.9345x; 1.0721x over previous
#include <cuda_runtime.h>
#include <cuda_fp16.h>
#include <mma.h>

using namespace nvcuda;

// ---------------------------------------------------------------------------
// Attention_50921132261730 — R9: transposed-weight GEMMs + norm fused in epi
//   t_f2h: Wqkv -> WqT fp16 [512][3072], Wout -> WoT fp16 [1024][512] (once)
//   qkv_gemm: C = WqT^T@x per batch; epilogue does l2norm(+scales)/v-convert
//             and writes qh/kh/vh fp16 directly (no fp32 intermediate)
//   flash: unchanged from R8 (fp16 WMMA, 2x2 warp split, 3 CTA/SM)
//   out_gemm: WoT^T @ aoh + bout (bias in accumulator init)
// ---------------------------------------------------------------------------

constexpr int Bb = 2, Cc = 512, Nn = 2048, HEADS = 16, DHEAD = 64;
constexpr int HDIM = HEADS * DHEAD;    // 1024
constexpr int BH = Bb * HEADS;         // 32

__device__ half g_WqT[Cc * 3 * HDIM];          // [512][3072]
__device__ half g_WoT[HDIM * Cc];              // [1024][512]
__device__ half g_xh [(long)Bb * Cc * Nn];
__device__ half g_qh [(long)BH * DHEAD * Nn];
__device__ half g_kh [(long)BH * DHEAD * Nn];
__device__ half g_vh [(long)BH * DHEAD * Nn];
__device__ half g_aoh[(long)Bb * HDIM * Nn];

__device__ __forceinline__ uint2 pack4h(float4 v) {
    half2 a = __floats2half2_rn(v.x, v.y);
    half2 b = __floats2half2_rn(v.z, v.w);
    uint2 r;
    r.x = *reinterpret_cast<unsigned*>(&a);
    r.y = *reinterpret_cast<unsigned*>(&b);
    return r;
}

// ---------------------------------------------------------------------------
// Tiled transpose + fp32->fp16: in [R][C] float -> out [C][R] half
// grid (C/32, R/32), block (32,8)
// ---------------------------------------------------------------------------
template<int R, int C>
__global__ void t_f2h(const float* __restrict__ src, half* __restrict__ dst)
{
    __shared__ float tile[32][33];
    const int c0 = blockIdx.x * 32, r0 = blockIdx.y * 32;
    const int tx = threadIdx.x, ty = threadIdx.y;
    #pragma unroll
    for (int i = 0; i < 4; i++)
        tile[ty*4 + i][tx] = src[(long)(r0 + ty*4 + i) * C + c0 + tx];
    __syncthreads();
    #pragma unroll
    for (int i = 0; i < 4; i++)
        dst[(long)(c0 + ty*4 + i) * R + r0 + tx] = __float2half_rn(tile[tx][ty*4 + i]);
}

// ---------------------------------------------------------------------------
// fp32 -> fp16 bulk convert (x)
// ---------------------------------------------------------------------------
__global__ void f2h_k(const float* __restrict__ src, half* __restrict__ dst)
{
    long i = ((long)blockIdx.x * 256 + threadIdx.x) * 8;
    float4 a = *(const float4*)(src + i);
    float4 b = *(const float4*)(src + i + 4);
    uint2 pa = pack4h(a), pb = pack4h(b);
    *(uint4*)(dst + i) = make_uint4(pa.x, pa.y, pb.x, pb.y);
}

// ---------------------------------------------------------------------------
// qkv GEMM with fused norm epilogue.
// A = WqT [K=512][M=3072] half (pre-transposed), B = xh [b][512][2048] half.
// grid (16, 24, 2), 256 threads. BM=128, BN=128, BK=32, warp 64x32.
// Epilogue: y<8 -> q heads (norm*8*q_scale), 8..15 -> k (norm*k_scale),
//           16..23 -> v (plain fp16). Two waves (one head each).
// ---------------------------------------------------------------------------
constexpr int QLDA = 136, QLDB = 136, QEPILD = 132;
constexpr int QKV_SMEM = 2 * 32 * (QLDA + QLDB) * 2;   // 34,816 B

__global__ void __launch_bounds__(256)
qkv_gemm(const half* __restrict__ WqT, const half* __restrict__ xh,
         const float* __restrict__ q_scale, const float* __restrict__ k_scale,
         half* __restrict__ qh, half* __restrict__ kh, half* __restrict__ vh)
{
    extern __shared__ char smc[];
    half*  As = (half*)smc;                     // [2][32*136]
    half*  Bs = As + 2 * 32 * QLDA;
    float* Cs = (float*)smc;                    // 64 x 132 epilogue alias

    const int tid = threadIdx.x, wid = tid >> 5;
    const int m0 = blockIdx.y * 128, n0 = blockIdx.x * 128, b = blockIdx.z;
    const int wm = (wid >> 2) * 64, wn = (wid & 3) * 32;
    const half* B = xh + (long)b * Cc * Nn;

    wmma::fragment<wmma::accumulator,16,16,16,float> acc[4][2];
    #pragma unroll
    for (int i = 0; i < 4; i++)
        #pragma unroll
        for (int j = 0; j < 2; j++) wmma::fill_fragment(acc[i][j], 0.f);

    uint4 ua[2], ub[2];
    auto ldg = [&](int k0) {
        #pragma unroll
        for (int g = 0; g < 2; g++) {
            int idx = tid + g*256, kk = idx >> 4, mq = idx & 15;
            ua[g] = *(const uint4*)(WqT + (long)(k0+kk)*(3*HDIM) + m0 + mq*8);
            ub[g] = *(const uint4*)(B + (long)(k0+kk)*Nn + n0 + mq*8);
        }
    };
    auto sts = [&](int buf) {
        #pragma unroll
        for (int g = 0; g < 2; g++) {
            int idx = tid + g*256, kk = idx >> 4, mq = idx & 15;
            *(uint4*)&As[buf*32*QLDA + kk*QLDA + mq*8] = ua[g];
            *(uint4*)&Bs[buf*32*QLDB + kk*QLDB + mq*8] = ub[g];
        }
    };

    ldg(0); sts(0); __syncthreads();

    #pragma unroll 1
    for (int it = 0; it < 16; it++) {
        const int cur = it & 1;
        if (it + 1 < 16) ldg((it + 1) * 32);
        #pragma unroll
        for (int kc = 0; kc < 32; kc += 16) {
            wmma::fragment<wmma::matrix_a,16,16,16,half,wmma::col_major> af[4];
            #pragma unroll
            for (int i = 0; i < 4; i++)
                wmma::load_matrix_sync(af[i], &As[cur*32*QLDA + kc*QLDA + wm + i*16], QLDA);
            #pragma unroll
            for (int j = 0; j < 2; j++) {
                wmma::fragment<wmma::matrix_b,16,16,16,half,wmma::row_major> bf;
                wmma::load_matrix_sync(bf, &Bs[cur*32*QLDB + kc*QLDB + wn + j*16], QLDB);
                #pragma unroll
                for (int i = 0; i < 4; i++)
                    wmma::mma_sync(acc[i][j], af[i], bf, acc[i][j]);
            }
        }
        if (it + 1 < 16) sts(cur ^ 1);
        __syncthreads();
    }

    // ---- epilogue: per-head fp32 tile -> norm/convert -> fp16 global ----
    const int type = blockIdx.y >> 3;       // 0=q, 1=k, 2=v
    const int yb   = blockIdx.y & 7;

    #pragma unroll 1
    for (int wave = 0; wave < 2; wave++) {
        if ((wid >> 2) == wave) {
            #pragma unroll
            for (int i = 0; i < 4; i++)
                #pragma unroll
                for (int j = 0; j < 2; j++)
                    wmma::store_matrix_sync(Cs + (i*16)*QEPILD + wn + j*16,
                                            acc[i][j], QEPILD, wmma::mem_row_major);
        }
        __syncthreads();
        if (tid < 128) {
            const int j = tid;
            const int h = yb*2 + wave;
            half* dst = (type == 0 ? qh : (type == 1 ? kh : vh))
                        + ((long)(b*HEADS + h) * DHEAD) * Nn + n0 + j;
            if (type == 2) {
                #pragma unroll
                for (int d = 0; d < DHEAD; d++)
                    dst[(long)d*Nn] = __float2half_rn(Cs[d*QEPILD + j]);
            } else {
                float ss = 0.f;
                #pragma unroll
                for (int d = 0; d < DHEAD; d++) {
                    float t = Cs[d*QEPILD + j];
                    ss += t * t;
                }
                float inv = (type ? 1.0f : 8.0f) / fmaxf(sqrtf(ss), 1e-12f);
                const float* sc = type ? k_scale : q_scale;
                #pragma unroll
                for (int d = 0; d < DHEAD; d++)
                    dst[(long)d*Nn] = __float2half_rn(Cs[d*QEPILD + j] * inv * sc[d]);
            }
        }
        __syncthreads();
    }
}

// ---------------------------------------------------------------------------
// out GEMM: A = WoT [1024][512] half (pre-transposed), B = aoh, + bias.
// grid (16, 8, 2), 256 threads. BM=64, BN=128, BK=32, warp 32x32.
// ---------------------------------------------------------------------------
constexpr int OLDA = 72, OLDB = 136;

__global__ void __launch_bounds__(256)
out_gemm(const half* __restrict__ WoT, const half* __restrict__ Bg,
         float* __restrict__ Cg, const float* __restrict__ bias)
{
    __shared__ half As[2][32 * OLDA];
    __shared__ half Bs[2][32 * OLDB];

    const half* B = Bg + (long)blockIdx.z * HDIM * Nn;
    float*      C = Cg + (long)blockIdx.z * Cc * Nn;
    const int tid = threadIdx.x, wid = tid >> 5;
    const int m0 = blockIdx.y * 64, n0 = blockIdx.x * 128;
    const int wm = (wid >> 2) * 32, wn = (wid & 3) * 32;

    wmma::fragment<wmma::accumulator,16,16,16,float> acc[2][2];
    {
        float* biasS = (float*)&As[0][0];   // 64 x 20 floats = 5120B < 9216B
        for (int l = tid; l < 64*20; l += 256)
            biasS[l] = bias[m0 + l/20];
        __syncthreads();
        #pragma unroll
        for (int i = 0; i < 2; i++)
            #pragma unroll
            for (int j = 0; j < 2; j++)
                wmma::load_matrix_sync(acc[i][j], biasS + (wm + i*16)*20, 20,
                                       wmma::mem_row_major);
        __syncthreads();
    }

    uint4 ua, ub[2];
    auto ldg = [&](int k0) {
        {
            int kk = tid >> 3, mq = tid & 7;
            ua = *(const uint4*)(WoT + (long)(k0+kk)*Cc + m0 + mq*8);
        }
        #pragma unroll
        for (int g = 0; g < 2; g++) {
            int idx = tid + g*256, kk = idx >> 4, nq = idx & 15;
            ub[g] = *(const uint4*)(B + (long)(k0+kk)*Nn + n0 + nq*8);
        }
    };
    auto sts = [&](int buf) {
        {
            int kk = tid >> 3, mq = tid & 7;
            *(uint4*)&As[buf][kk*OLDA + mq*8] = ua;
        }
        #pragma unroll
        for (int g = 0; g < 2; g++) {
            int idx = tid + g*256, kk = idx >> 4, nq = idx & 15;
            *(uint4*)&Bs[buf][kk*OLDB + nq*8] = ub[g];
        }
    };

    ldg(0); sts(0); __syncthreads();

    #pragma unroll 1
    for (int it = 0; it < 32; it++) {
        const int cur = it & 1;
        if (it + 1 < 32) ldg((it + 1) * 32);
        #pragma unroll
        for (int kc = 0; kc < 32; kc += 16) {
            wmma::fragment<wmma::matrix_a,16,16,16,half,wmma::col_major> af[2];
            #pragma unroll
            for (int i = 0; i < 2; i++)
                wmma::load_matrix_sync(af[i], &As[cur][kc*OLDA + wm + i*16], OLDA);
            #pragma unroll
            for (int j = 0; j < 2; j++) {
                wmma::fragment<wmma::matrix_b,16,16,16,half,wmma::row_major> bf;
                wmma::load_matrix_sync(bf, &Bs[cur][kc*OLDB + wn + j*16], OLDB);
                #pragma unroll
                for (int i = 0; i < 2; i++)
                    wmma::mma_sync(acc[i][j], af[i], bf, acc[i][j]);
            }
        }
        if (it + 1 < 32) sts(cur ^ 1);
        __syncthreads();
    }

    #pragma unroll
    for (int i = 0; i < 2; i++)
        #pragma unroll
        for (int j = 0; j < 2; j++)
            wmma::store_matrix_sync(C + (long)(m0+wm+i*16)*Nn + n0 + wn + j*16,
                                    acc[i][j], Nn, wmma::mem_row_major);
}

// ---------------------------------------------------------------------------
// Flash attention (unchanged from R8): fp16 WMMA, 2x2 warp split, 3 CTA/SM.
// ---------------------------------------------------------------------------
constexpr int FLH  = 136;
constexpr int QLH  = 72;
constexpr int SLDf = 68;
constexpr int PLH  = 136;
constexpr int KS_B = 0;
constexpr int VS_B = 17408;
constexpr int SF_B = 34816;
constexpr int RS_B = 69632;
constexpr int FLASH_SMEM = 70144;

__global__ void __launch_bounds__(128, 3)
flash_h(const half* __restrict__ qhg, const half* __restrict__ khg,
        const half* __restrict__ vhg, half* __restrict__ aoh)
{
    extern __shared__ char smc[];
    half*  Ks = (half*)(smc + KS_B);
    half*  Vs = (half*)(smc + VS_B);
    float* Sf = (float*)(smc + SF_B);
    float* rs = (float*)(smc + RS_B);
    half*  Qst = (half*)(smc + SF_B);

    const int tid = threadIdx.x, wid = tid >> 5, lane = tid & 31;
    const int r = wid >> 1, c = wid & 1;
    const int qi0 = blockIdx.x * 64;
    const int bh = blockIdx.y;
    const int b = bh >> 4, h = bh & 15;

    const half* qg = qhg + (long)bh * DHEAD * Nn;
    const half* kg = khg + (long)bh * DHEAD * Nn;
    const half* vg = vhg + (long)bh * DHEAD * Nn;

    for (int l = tid; l < 64*8; l += 128) {
        int d = l >> 3, i8 = (l & 7) * 8;
        *(uint4*)&Qst[d*QLH + i8] = *(const uint4*)(qg + (long)d*Nn + qi0 + i8);
    }
    __syncthreads();

    wmma::fragment<wmma::matrix_a,16,16,16,half,wmma::col_major> qf[2][4];
    #pragma unroll
    for (int m = 0; m < 2; m++)
        #pragma unroll
        for (int kc = 0; kc < 4; kc++)
            wmma::load_matrix_sync(qf[m][kc], Qst + kc*16*QLH + r*32 + m*16, QLH);

    wmma::fragment<wmma::accumulator,16,16,16,float> of[2][4];
    #pragma unroll
    for (int m = 0; m < 2; m++)
        #pragma unroll
        for (int dt = 0; dt < 4; dt++) wmma::fill_fragment(of[m][dt], 0.f);

    float rowsum = 0.f;
    float* Sw  = Sf + wid * (32*SLDf);
    half*  Phw = (half*)Sw;
    __syncthreads();

    for (int kt = 0; kt < Nn; kt += 128) {
        for (int l = tid; l < 64*16; l += 128) {
            int d = l >> 4, j8 = (l & 15) * 8;
            *(uint4*)&Ks[d*FLH + j8] = *(const uint4*)(kg + (long)d*Nn + kt + j8);
            *(uint4*)&Vs[d*FLH + j8] = *(const uint4*)(vg + (long)d*Nn + kt + j8);
        }
        __syncthreads();

        #pragma unroll
        for (int jg = 0; jg < 2; jg++) {
            wmma::fragment<wmma::accumulator,16,16,16,float> sf[2][2];
            #pragma unroll
            for (int m = 0; m < 2; m++)
                #pragma unroll
                for (int jj = 0; jj < 2; jj++) wmma::fill_fragment(sf[m][jj], 0.f);
            #pragma unroll
            for (int kc = 0; kc < 4; kc++) {
                #pragma unroll
                for (int jj = 0; jj < 2; jj++) {
                    wmma::fragment<wmma::matrix_b,16,16,16,half,wmma::row_major> bf;
                    wmma::load_matrix_sync(bf, Ks + kc*16*FLH + c*64 + (jg*2+jj)*16, FLH);
                    wmma::mma_sync(sf[0][jj], qf[0][kc], bf, sf[0][jj]);
                    wmma::mma_sync(sf[1][jj], qf[1][kc], bf, sf[1][jj]);
                }
            }
            #pragma unroll
            for (int m = 0; m < 2; m++)
                #pragma unroll
                for (int jj = 0; jj < 2; jj++)
                    wmma::store_matrix_sync(Sw + m*16*SLDf + (jg*2+jj)*16,
                                            sf[m][jj], SLDf, wmma::mem_row_major);
        }
        __syncwarp();

        {
            float* prow = Sw + lane*SLDf;
            half*  drow = (half*)prow;
            float s = 0.f;
            {
                float4 t[8];
                #pragma unroll
                for (int g = 0; g < 8; g++) {
                    float4 v = ((const float4*)prow)[g];
                    v.x = __expf(v.x); v.y = __expf(v.y);
                    v.z = __expf(v.z); v.w = __expf(v.w);
                    s += v.x + v.y + v.z + v.w;
                    t[g] = v;
                }
                #pragma unroll
                for (int g = 0; g < 4; g++) {
                    uint2 a = pack4h(t[2*g]), bq = pack4h(t[2*g+1]);
                    ((uint4*)drow)[g] = make_uint4(a.x, a.y, bq.x, bq.y);
                }
            }
            {
                float4 t[8];
                #pragma unroll
                for (int g = 0; g < 8; g++) {
                    float4 v = ((const float4*)prow)[8+g];
                    v.x = __expf(v.x); v.y = __expf(v.y);
                    v.z = __expf(v.z); v.w = __expf(v.w);
                    s += v.x + v.y + v.z + v.w;
                    t[g] = v;
                }
                #pragma unroll
                for (int g = 0; g < 4; g++) {
                    uint2 a = pack4h(t[2*g]), bq = pack4h(t[2*g+1]);
                    ((uint4*)drow)[4+g] = make_uint4(a.x, a.y, bq.x, bq.y);
                }
            }
            rowsum += s;
        }
        __syncwarp();

        #pragma unroll
        for (int kc = 0; kc < 4; kc++) {
            wmma::fragment<wmma::matrix_a,16,16,16,half,wmma::row_major> af[2];
            #pragma unroll
            for (int m = 0; m < 2; m++)
                wmma::load_matrix_sync(af[m], Phw + m*16*PLH + kc*16, PLH);
            #pragma unroll
            for (int dt = 0; dt < 4; dt++) {
                wmma::fragment<wmma::matrix_b,16,16,16,half,wmma::col_major> bf;
                wmma::load_matrix_sync(bf, Vs + dt*16*FLH + c*64 + kc*16, FLH);
                wmma::mma_sync(of[0][dt], af[0], bf, of[0][dt]);
                wmma::mma_sync(of[1][dt], af[1], bf, of[1][dt]);
            }
        }
        __syncthreads();
    }

    #pragma unroll
    for (int m = 0; m < 2; m++)
        #pragma unroll
        for (int dt = 0; dt < 4; dt++)
            wmma::store_matrix_sync(Sw + m*16*SLDf + dt*16, of[m][dt], SLDf,
                                    wmma::mem_row_major);
    rs[wid*32 + lane] = rowsum;
    __syncthreads();

    {
        const int i = tid & 63, db = (tid >> 6) * 32;
        const int wA = (i >> 5) * 2, il = i & 31;
        float inv = 1.0f / (rs[wA*32 + il] + rs[(wA+1)*32 + il]);
        const float* SA = Sf + wA*(32*SLDf) + il*SLDf;
        const float* SB = SA + 32*SLDf;
        half* aog = aoh + ((long)b*HDIM + h*DHEAD)*Nn + qi0 + i;
        #pragma unroll
        for (int d = 0; d < 32; d++) {
            int dd = db + d;
            aog[(long)dd*Nn] = __float2half_rn((SA[dd] + SB[dd]) * inv);
        }
    }
}

// ---------------------------------------------------------------------------
extern "C" void kernel_launch(void* const* d_in, const int* in_sizes, int n_in,
                              void* d_out, int out_size)
{
    (void)in_sizes; (void)n_in; (void)out_size;
    const float* x       = (const float*)d_in[0];
    const float* Wqkv    = (const float*)d_in[1];
    const float* q_scale = (const float*)d_in[2];
    const float* k_scale = (const float*)d_in[3];
    const float* Wout    = (const float*)d_in[4];
    const float* bout    = (const float*)d_in[5];
    float* out = (float*)d_out;

    half *WqT, *WoT, *xh, *qh, *kh, *vh, *aoh;
    cudaGetSymbolAddress((void**)&WqT, g_WqT);
    cudaGetSymbolAddress((void**)&WoT, g_WoT);
    cudaGetSymbolAddress((void**)&xh,  g_xh);
    cudaGetSymbolAddress((void**)&qh,  g_qh);
    cudaGetSymbolAddress((void**)&kh,  g_kh);
    cudaGetSymbolAddress((void**)&vh,  g_vh);
    cudaGetSymbolAddress((void**)&aoh, g_aoh);

    cudaFuncSetAttribute(flash_h, cudaFuncAttributeMaxDynamicSharedMemorySize,
                         FLASH_SMEM);

    // 0) one-time transposed fp16 weights + x convert
    t_f2h<3*HDIM, Cc><<<dim3(Cc/32, 3*HDIM/32), dim3(32,8)>>>(Wqkv, WqT);
    t_f2h<Cc, HDIM><<<dim3(HDIM/32, Cc/32), dim3(32,8)>>>(Wout, WoT);
    f2h_k<<<(int)(((long)Bb*Cc*Nn)/2048), 256>>>(x, xh);

    // 1) qkv gemm + fused norm/scale/v-convert -> qh, kh, vh (fp16)
    qkv_gemm<<<dim3(Nn/128, 24, Bb), 256, QKV_SMEM>>>(
        WqT, xh, q_scale, k_scale, qh, kh, vh);

    // 2) flash attention -> aoh (fp16, channel-major)
    flash_h<<<dim3(Nn/64, BH), 128, FLASH_SMEM>>>(qh, kh, vh, aoh);

    // 3) out = WoT^T @ aoh + bout
    out_gemm<<<dim3(Nn/128, Cc/64, Bb), 256>>>(WoT, aoh, out, bout);
}

// round 11
// speedup vs baseline: 3.3340x; 1.1361x over previous
#include <cuda_runtime.h>
#include <cuda_fp16.h>
#include <mma.h>
#include <cstdint>

using namespace nvcuda;

// ---------------------------------------------------------------------------
// Attention_50921132261730 — R11 (= R10 + missing <cstdint>):
//   t_f2h: Wqkv -> WqT fp16 [512][3072], Wout -> WoT fp16 [1024][512] (once)
//   qkv_gemm: BM=64 (one head/CTA), fused l2norm/scale/v epilogue -> qh/kh/vh
//   flash: fp16 WMMA 2x2 warp split, 3 CTA/SM, cp.async K/V fills
//   out_gemm: WoT^T @ aoh + bout (bias in accumulator init)
// ---------------------------------------------------------------------------

constexpr int Bb = 2, Cc = 512, Nn = 2048, HEADS = 16, DHEAD = 64;
constexpr int HDIM = HEADS * DHEAD;    // 1024
constexpr int BH = Bb * HEADS;         // 32

__device__ half g_WqT[Cc * 3 * HDIM];          // [512][3072]
__device__ half g_WoT[HDIM * Cc];              // [1024][512]
__device__ half g_xh [(long)Bb * Cc * Nn];
__device__ half g_qh [(long)BH * DHEAD * Nn];
__device__ half g_kh [(long)BH * DHEAD * Nn];
__device__ half g_vh [(long)BH * DHEAD * Nn];
__device__ half g_aoh[(long)Bb * HDIM * Nn];

__device__ __forceinline__ uint2 pack4h(float4 v) {
    half2 a = __floats2half2_rn(v.x, v.y);
    half2 b = __floats2half2_rn(v.z, v.w);
    uint2 r;
    r.x = *reinterpret_cast<unsigned*>(&a);
    r.y = *reinterpret_cast<unsigned*>(&b);
    return r;
}
__device__ __forceinline__ void cp16(unsigned int s, const void* g) {
    asm volatile("cp.async.cg.shared.global [%0], [%1], 16;" :: "r"(s), "l"(g));
}

// ---------------------------------------------------------------------------
// Tiled transpose + fp32->fp16: in [R][C] float -> out [C][R] half
// ---------------------------------------------------------------------------
template<int R, int C>
__global__ void t_f2h(const float* __restrict__ src, half* __restrict__ dst)
{
    __shared__ float tile[32][33];
    const int c0 = blockIdx.x * 32, r0 = blockIdx.y * 32;
    const int tx = threadIdx.x, ty = threadIdx.y;
    #pragma unroll
    for (int i = 0; i < 4; i++)
        tile[ty*4 + i][tx] = src[(long)(r0 + ty*4 + i) * C + c0 + tx];
    __syncthreads();
    #pragma unroll
    for (int i = 0; i < 4; i++)
        dst[(long)(c0 + ty*4 + i) * R + r0 + tx] = __float2half_rn(tile[tx][ty*4 + i]);
}

__global__ void f2h_k(const float* __restrict__ src, half* __restrict__ dst)
{
    long i = ((long)blockIdx.x * 256 + threadIdx.x) * 8;
    float4 a = *(const float4*)(src + i);
    float4 b = *(const float4*)(src + i + 4);
    uint2 pa = pack4h(a), pb = pack4h(b);
    *(uint4*)(dst + i) = make_uint4(pa.x, pa.y, pb.x, pb.y);
}

// ---------------------------------------------------------------------------
// qkv GEMM, one head per CTA (BM=64), fused norm epilogue.
// A = WqT [512][3072], B = xh [b][512][2048]. grid (16, 48, 2), 256 thr.
// BK=32, warp 32x32 (2x4 warp grid). blockIdx.y: type = y>>4, head = y&15.
// ---------------------------------------------------------------------------
constexpr int QLDA = 72, QLDB = 136, QEPILD = 132;
constexpr int QKV_SMEM = 64 * QEPILD * 4;      // 33,792 B (covers GEMM bufs 26,624)

__global__ void __launch_bounds__(256, 2)
qkv_gemm(const half* __restrict__ WqT, const half* __restrict__ xh,
         const float* __restrict__ q_scale, const float* __restrict__ k_scale,
         half* __restrict__ qh, half* __restrict__ kh, half* __restrict__ vh)
{
    extern __shared__ char smc[];
    half*  As = (half*)smc;                    // [2][32*72]   = 9216 B
    half*  Bs = (half*)(smc + 9216);           // [2][32*136]  = 17408 B
    float* Cs = (float*)smc;                   // 64 x 132 epilogue alias

    const int tid = threadIdx.x, wid = tid >> 5;
    const int m0 = blockIdx.y * 64, n0 = blockIdx.x * 128, b = blockIdx.z;
    const int wm = (wid >> 2) * 32, wn = (wid & 3) * 32;
    const half* B = xh + (long)b * Cc * Nn;

    wmma::fragment<wmma::accumulator,16,16,16,float> acc[2][2];
    #pragma unroll
    for (int i = 0; i < 2; i++)
        #pragma unroll
        for (int j = 0; j < 2; j++) wmma::fill_fragment(acc[i][j], 0.f);

    uint4 ua, ub[2];
    auto ldg = [&](int k0) {
        {
            int kk = tid >> 3, mq = tid & 7;
            ua = *(const uint4*)(WqT + (long)(k0+kk)*(3*HDIM) + m0 + mq*8);
        }
        #pragma unroll
        for (int g = 0; g < 2; g++) {
            int idx = tid + g*256, kk = idx >> 4, nq = idx & 15;
            ub[g] = *(const uint4*)(B + (long)(k0+kk)*Nn + n0 + nq*8);
        }
    };
    auto sts = [&](int buf) {
        {
            int kk = tid >> 3, mq = tid & 7;
            *(uint4*)&As[buf*32*QLDA + kk*QLDA + mq*8] = ua;
        }
        #pragma unroll
        for (int g = 0; g < 2; g++) {
            int idx = tid + g*256, kk = idx >> 4, nq = idx & 15;
            *(uint4*)&Bs[buf*32*QLDB + kk*QLDB + nq*8] = ub[g];
        }
    };

    ldg(0); sts(0); __syncthreads();

    #pragma unroll 1
    for (int it = 0; it < 16; it++) {
        const int cur = it & 1;
        if (it + 1 < 16) ldg((it + 1) * 32);
        #pragma unroll
        for (int kc = 0; kc < 32; kc += 16) {
            wmma::fragment<wmma::matrix_a,16,16,16,half,wmma::col_major> af[2];
            #pragma unroll
            for (int i = 0; i < 2; i++)
                wmma::load_matrix_sync(af[i], &As[cur*32*QLDA + kc*QLDA + wm + i*16], QLDA);
            #pragma unroll
            for (int j = 0; j < 2; j++) {
                wmma::fragment<wmma::matrix_b,16,16,16,half,wmma::row_major> bf;
                wmma::load_matrix_sync(bf, &Bs[cur*32*QLDB + kc*QLDB + wn + j*16], QLDB);
                #pragma unroll
                for (int i = 0; i < 2; i++)
                    wmma::mma_sync(acc[i][j], af[i], bf, acc[i][j]);
            }
        }
        if (it + 1 < 16) sts(cur ^ 1);
        __syncthreads();
    }

    // ---- epilogue: whole 64x128 fp32 tile -> smem -> norm/convert ----
    #pragma unroll
    for (int i = 0; i < 2; i++)
        #pragma unroll
        for (int j = 0; j < 2; j++)
            wmma::store_matrix_sync(Cs + (wm + i*16)*QEPILD + wn + j*16,
                                    acc[i][j], QEPILD, wmma::mem_row_major);
    __syncthreads();

    {
        const int type = blockIdx.y >> 4;      // 0=q, 1=k, 2=v
        const int h    = blockIdx.y & 15;
        const int j    = tid & 127;
        const int d0   = (tid >> 7) * 32;      // each half of CTA writes 32 d's
        half* dst = (type == 0 ? qh : (type == 1 ? kh : vh))
                    + ((long)(b*HEADS + h) * DHEAD) * Nn + n0 + j;
        if (type == 2) {
            #pragma unroll
            for (int d = 0; d < 32; d++)
                dst[(long)(d0+d)*Nn] = __float2half_rn(Cs[(d0+d)*QEPILD + j]);
        } else {
            float ss = 0.f;
            #pragma unroll
            for (int d = 0; d < DHEAD; d++) {
                float t = Cs[d*QEPILD + j];
                ss += t * t;
            }
            float inv = (type ? 1.0f : 8.0f) / fmaxf(sqrtf(ss), 1e-12f);
            const float* sc = type ? k_scale : q_scale;
            #pragma unroll
            for (int d = 0; d < 32; d++)
                dst[(long)(d0+d)*Nn] =
                    __float2half_rn(Cs[(d0+d)*QEPILD + j] * inv * sc[d0+d]);
        }
    }
}

// ---------------------------------------------------------------------------
// out GEMM: A = WoT [1024][512] half, B = aoh, + bias (accumulator init).
// ---------------------------------------------------------------------------
constexpr int OLDA = 72, OLDB = 136;

__global__ void __launch_bounds__(256)
out_gemm(const half* __restrict__ WoT, const half* __restrict__ Bg,
         float* __restrict__ Cg, const float* __restrict__ bias)
{
    __shared__ half As[2][32 * OLDA];
    __shared__ half Bs[2][32 * OLDB];

    const half* B = Bg + (long)blockIdx.z * HDIM * Nn;
    float*      C = Cg + (long)blockIdx.z * Cc * Nn;
    const int tid = threadIdx.x, wid = tid >> 5;
    const int m0 = blockIdx.y * 64, n0 = blockIdx.x * 128;
    const int wm = (wid >> 2) * 32, wn = (wid & 3) * 32;

    wmma::fragment<wmma::accumulator,16,16,16,float> acc[2][2];
    {
        float* biasS = (float*)&As[0][0];
        for (int l = tid; l < 64*20; l += 256)
            biasS[l] = bias[m0 + l/20];
        __syncthreads();
        #pragma unroll
        for (int i = 0; i < 2; i++)
            #pragma unroll
            for (int j = 0; j < 2; j++)
                wmma::load_matrix_sync(acc[i][j], biasS + (wm + i*16)*20, 20,
                                       wmma::mem_row_major);
        __syncthreads();
    }

    uint4 ua, ub[2];
    auto ldg = [&](int k0) {
        {
            int kk = tid >> 3, mq = tid & 7;
            ua = *(const uint4*)(WoT + (long)(k0+kk)*Cc + m0 + mq*8);
        }
        #pragma unroll
        for (int g = 0; g < 2; g++) {
            int idx = tid + g*256, kk = idx >> 4, nq = idx & 15;
            ub[g] = *(const uint4*)(B + (long)(k0+kk)*Nn + n0 + nq*8);
        }
    };
    auto sts = [&](int buf) {
        {
            int kk = tid >> 3, mq = tid & 7;
            *(uint4*)&As[buf][kk*OLDA + mq*8] = ua;
        }
        #pragma unroll
        for (int g = 0; g < 2; g++) {
            int idx = tid + g*256, kk = idx >> 4, nq = idx & 15;
            *(uint4*)&Bs[buf][kk*OLDB + nq*8] = ub[g];
        }
    };

    ldg(0); sts(0); __syncthreads();

    #pragma unroll 1
    for (int it = 0; it < 32; it++) {
        const int cur = it & 1;
        if (it + 1 < 32) ldg((it + 1) * 32);
        #pragma unroll
        for (int kc = 0; kc < 32; kc += 16) {
            wmma::fragment<wmma::matrix_a,16,16,16,half,wmma::col_major> af[2];
            #pragma unroll
            for (int i = 0; i < 2; i++)
                wmma::load_matrix_sync(af[i], &As[cur][kc*OLDA + wm + i*16], OLDA);
            #pragma unroll
            for (int j = 0; j < 2; j++) {
                wmma::fragment<wmma::matrix_b,16,16,16,half,wmma::row_major> bf;
                wmma::load_matrix_sync(bf, &Bs[cur][kc*OLDB + wn + j*16], OLDB);
                #pragma unroll
                for (int i = 0; i < 2; i++)
                    wmma::mma_sync(acc[i][j], af[i], bf, acc[i][j]);
            }
        }
        if (it + 1 < 32) sts(cur ^ 1);
        __syncthreads();
    }

    #pragma unroll
    for (int i = 0; i < 2; i++)
        #pragma unroll
        for (int j = 0; j < 2; j++)
            wmma::store_matrix_sync(C + (long)(m0+wm+i*16)*Nn + n0 + wn + j*16,
                                    acc[i][j], Nn, wmma::mem_row_major);
}

// ---------------------------------------------------------------------------
// Flash attention: fp16 WMMA, 2x2 warp split, 3 CTA/SM, cp.async K/V fills.
// ---------------------------------------------------------------------------
constexpr int FLH  = 136;
constexpr int QLH  = 72;
constexpr int SLDf = 68;
constexpr int PLH  = 136;
constexpr int KS_B = 0;
constexpr int VS_B = 17408;
constexpr int SF_B = 34816;
constexpr int RS_B = 69632;
constexpr int FLASH_SMEM = 70144;

__global__ void __launch_bounds__(128, 3)
flash_h(const half* __restrict__ qhg, const half* __restrict__ khg,
        const half* __restrict__ vhg, half* __restrict__ aoh)
{
    extern __shared__ char smc[];
    half*  Ks = (half*)(smc + KS_B);
    half*  Vs = (half*)(smc + VS_B);
    float* Sf = (float*)(smc + SF_B);
    float* rs = (float*)(smc + RS_B);
    half*  Qst = (half*)(smc + SF_B);

    const int tid = threadIdx.x, wid = tid >> 5, lane = tid & 31;
    const int r = wid >> 1, c = wid & 1;
    const int qi0 = blockIdx.x * 64;
    const int bh = blockIdx.y;
    const int b = bh >> 4, h = bh & 15;

    const half* qg = qhg + (long)bh * DHEAD * Nn;
    const half* kg = khg + (long)bh * DHEAD * Nn;
    const half* vg = vhg + (long)bh * DHEAD * Nn;
    const unsigned int ksb = (unsigned int)__cvta_generic_to_shared(Ks);
    const unsigned int vsb = (unsigned int)__cvta_generic_to_shared(Vs);

    for (int l = tid; l < 64*8; l += 128) {
        int d = l >> 3, i8 = (l & 7) * 8;
        *(uint4*)&Qst[d*QLH + i8] = *(const uint4*)(qg + (long)d*Nn + qi0 + i8);
    }
    __syncthreads();

    wmma::fragment<wmma::matrix_a,16,16,16,half,wmma::col_major> qf[2][4];
    #pragma unroll
    for (int m = 0; m < 2; m++)
        #pragma unroll
        for (int kc = 0; kc < 4; kc++)
            wmma::load_matrix_sync(qf[m][kc], Qst + kc*16*QLH + r*32 + m*16, QLH);

    wmma::fragment<wmma::accumulator,16,16,16,float> of[2][4];
    #pragma unroll
    for (int m = 0; m < 2; m++)
        #pragma unroll
        for (int dt = 0; dt < 4; dt++) wmma::fill_fragment(of[m][dt], 0.f);

    float rowsum = 0.f;
    float* Sw  = Sf + wid * (32*SLDf);
    half*  Phw = (half*)Sw;
    __syncthreads();

    for (int kt = 0; kt < Nn; kt += 128) {
        // ---- K,V fills via cp.async ----
        #pragma unroll
        for (int g = 0; g < 8; g++) {
            int l = tid + g*128;
            int d = l >> 4, j8 = (l & 15) * 8;
            cp16(ksb + (d*FLH + j8)*2, kg + (long)d*Nn + kt + j8);
            cp16(vsb + (d*FLH + j8)*2, vg + (long)d*Nn + kt + j8);
        }
        asm volatile("cp.async.commit_group;" ::: "memory");
        asm volatile("cp.async.wait_group 0;" ::: "memory");
        __syncthreads();

        #pragma unroll
        for (int jg = 0; jg < 2; jg++) {
            wmma::fragment<wmma::accumulator,16,16,16,float> sf[2][2];
            #pragma unroll
            for (int m = 0; m < 2; m++)
                #pragma unroll
                for (int jj = 0; jj < 2; jj++) wmma::fill_fragment(sf[m][jj], 0.f);
            #pragma unroll
            for (int kc = 0; kc < 4; kc++) {
                #pragma unroll
                for (int jj = 0; jj < 2; jj++) {
                    wmma::fragment<wmma::matrix_b,16,16,16,half,wmma::row_major> bf;
                    wmma::load_matrix_sync(bf, Ks + kc*16*FLH + c*64 + (jg*2+jj)*16, FLH);
                    wmma::mma_sync(sf[0][jj], qf[0][kc], bf, sf[0][jj]);
                    wmma::mma_sync(sf[1][jj], qf[1][kc], bf, sf[1][jj]);
                }
            }
            #pragma unroll
            for (int m = 0; m < 2; m++)
                #pragma unroll
                for (int jj = 0; jj < 2; jj++)
                    wmma::store_matrix_sync(Sw + m*16*SLDf + (jg*2+jj)*16,
                                            sf[m][jj], SLDf, wmma::mem_row_major);
        }
        __syncwarp();

        {
            float* prow = Sw + lane*SLDf;
            half*  drow = (half*)prow;
            float s = 0.f;
            {
                float4 t[8];
                #pragma unroll
                for (int g = 0; g < 8; g++) {
                    float4 v = ((const float4*)prow)[g];
                    v.x = __expf(v.x); v.y = __expf(v.y);
                    v.z = __expf(v.z); v.w = __expf(v.w);
                    s += v.x + v.y + v.z + v.w;
                    t[g] = v;
                }
                #pragma unroll
                for (int g = 0; g < 4; g++) {
                    uint2 a = pack4h(t[2*g]), bq = pack4h(t[2*g+1]);
                    ((uint4*)drow)[g] = make_uint4(a.x, a.y, bq.x, bq.y);
                }
            }
            {
                float4 t[8];
                #pragma unroll
                for (int g = 0; g < 8; g++) {
                    float4 v = ((const float4*)prow)[8+g];
                    v.x = __expf(v.x); v.y = __expf(v.y);
                    v.z = __expf(v.z); v.w = __expf(v.w);
                    s += v.x + v.y + v.z + v.w;
                    t[g] = v;
                }
                #pragma unroll
                for (int g = 0; g < 4; g++) {
                    uint2 a = pack4h(t[2*g]), bq = pack4h(t[2*g+1]);
                    ((uint4*)drow)[4+g] = make_uint4(a.x, a.y, bq.x, bq.y);
                }
            }
            rowsum += s;
        }
        __syncwarp();

        #pragma unroll
        for (int kc = 0; kc < 4; kc++) {
            wmma::fragment<wmma::matrix_a,16,16,16,half,wmma::row_major> af[2];
            #pragma unroll
            for (int m = 0; m < 2; m++)
                wmma::load_matrix_sync(af[m], Phw + m*16*PLH + kc*16, PLH);
            #pragma unroll
            for (int dt = 0; dt < 4; dt++) {
                wmma::fragment<wmma::matrix_b,16,16,16,half,wmma::col_major> bf;
                wmma::load_matrix_sync(bf, Vs + dt*16*FLH + c*64 + kc*16, FLH);
                wmma::mma_sync(of[0][dt], af[0], bf, of[0][dt]);
                wmma::mma_sync(of[1][dt], af[1], bf, of[1][dt]);
            }
        }
        __syncthreads();
    }

    #pragma unroll
    for (int m = 0; m < 2; m++)
        #pragma unroll
        for (int dt = 0; dt < 4; dt++)
            wmma::store_matrix_sync(Sw + m*16*SLDf + dt*16, of[m][dt], SLDf,
                                    wmma::mem_row_major);
    rs[wid*32 + lane] = rowsum;
    __syncthreads();

    {
        const int i = tid & 63, db = (tid >> 6) * 32;
        const int wA = (i >> 5) * 2, il = i & 31;
        float inv = 1.0f / (rs[wA*32 + il] + rs[(wA+1)*32 + il]);
        const float* SA = Sf + wA*(32*SLDf) + il*SLDf;
        const float* SB = SA + 32*SLDf;
        half* aog = aoh + ((long)b*HDIM + h*DHEAD)*Nn + qi0 + i;
        #pragma unroll
        for (int d = 0; d < 32; d++) {
            int dd = db + d;
            aog[(long)dd*Nn] = __float2half_rn((SA[dd] + SB[dd]) * inv);
        }
    }
}

// ---------------------------------------------------------------------------
extern "C" void kernel_launch(void* const* d_in, const int* in_sizes, int n_in,
                              void* d_out, int out_size)
{
    (void)in_sizes; (void)n_in; (void)out_size;
    const float* x       = (const float*)d_in[0];
    const float* Wqkv    = (const float*)d_in[1];
    const float* q_scale = (const float*)d_in[2];
    const float* k_scale = (const float*)d_in[3];
    const float* Wout    = (const float*)d_in[4];
    const float* bout    = (const float*)d_in[5];
    float* out = (float*)d_out;

    half *WqT, *WoT, *xh, *qh, *kh, *vh, *aoh;
    cudaGetSymbolAddress((void**)&WqT, g_WqT);
    cudaGetSymbolAddress((void**)&WoT, g_WoT);
    cudaGetSymbolAddress((void**)&xh,  g_xh);
    cudaGetSymbolAddress((void**)&qh,  g_qh);
    cudaGetSymbolAddress((void**)&kh,  g_kh);
    cudaGetSymbolAddress((void**)&vh,  g_vh);
    cudaGetSymbolAddress((void**)&aoh, g_aoh);

    cudaFuncSetAttribute(flash_h, cudaFuncAttributeMaxDynamicSharedMemorySize,
                         FLASH_SMEM);

    // 0) one-time transposed fp16 weights + x convert
    t_f2h<3*HDIM, Cc><<<dim3(Cc/32, 3*HDIM/32), dim3(32,8)>>>(Wqkv, WqT);
    t_f2h<Cc, HDIM><<<dim3(HDIM/32, Cc/32), dim3(32,8)>>>(Wout, WoT);
    f2h_k<<<(int)(((long)Bb*Cc*Nn)/2048), 256>>>(x, xh);

    // 1) qkv gemm + fused norm/scale/v-convert -> qh, kh, vh (fp16)
    qkv_gemm<<<dim3(Nn/128, 48, Bb), 256, QKV_SMEM>>>(
        WqT, xh, q_scale, k_scale, qh, kh, vh);

    // 2) flash attention -> aoh (fp16, channel-major)
    flash_h<<<dim3(Nn/64, BH), 128, FLASH_SMEM>>>(qh, kh, vh, aoh);

    // 3) out = WoT^T @ aoh + bout
    out_gemm<<<dim3(Nn/128, Cc/64, Bb), 256>>>(WoT, aoh, out, bout);
}

// round 12
// speedup vs baseline: 3.6385x; 1.0913x over previous
#include <cuda_runtime.h>
#include <cuda_fp16.h>
#include <mma.h>
#include <cstdint>

using namespace nvcuda;

// ---------------------------------------------------------------------------
// Attention_50921132261730 — R12: 4-warp 64x32-tile GEMMs w/ cp.async pipeline
//   t_f2h: Wqkv -> WqT fp16 [512][3072], Wout -> WoT fp16 [1024][512] (once)
//   qkv_gemm: 128 thr, warp 64x32, cp.async DB, fused norm epilogue
//   flash: unchanged from R11 (fp16 WMMA 2x2 split, 3 CTA/SM, cp.async)
//   out_gemm: 128 thr, warp 64x32, cp.async DB, bias in accumulator init
// ---------------------------------------------------------------------------

constexpr int Bb = 2, Cc = 512, Nn = 2048, HEADS = 16, DHEAD = 64;
constexpr int HDIM = HEADS * DHEAD;    // 1024
constexpr int BH = Bb * HEADS;         // 32

__device__ half g_WqT[Cc * 3 * HDIM];          // [512][3072]
__device__ half g_WoT[HDIM * Cc];              // [1024][512]
__device__ half g_xh [(long)Bb * Cc * Nn];
__device__ half g_qh [(long)BH * DHEAD * Nn];
__device__ half g_kh [(long)BH * DHEAD * Nn];
__device__ half g_vh [(long)BH * DHEAD * Nn];
__device__ half g_aoh[(long)Bb * HDIM * Nn];

__device__ __forceinline__ uint2 pack4h(float4 v) {
    half2 a = __floats2half2_rn(v.x, v.y);
    half2 b = __floats2half2_rn(v.z, v.w);
    uint2 r;
    r.x = *reinterpret_cast<unsigned*>(&a);
    r.y = *reinterpret_cast<unsigned*>(&b);
    return r;
}
__device__ __forceinline__ void cp16(unsigned int s, const void* g) {
    asm volatile("cp.async.cg.shared.global [%0], [%1], 16;" :: "r"(s), "l"(g));
}

// ---------------------------------------------------------------------------
// Tiled transpose + fp32->fp16: in [R][C] float -> out [C][R] half
// ---------------------------------------------------------------------------
template<int R, int C>
__global__ void t_f2h(const float* __restrict__ src, half* __restrict__ dst)
{
    __shared__ float tile[32][33];
    const int c0 = blockIdx.x * 32, r0 = blockIdx.y * 32;
    const int tx = threadIdx.x, ty = threadIdx.y;
    #pragma unroll
    for (int i = 0; i < 4; i++)
        tile[ty*4 + i][tx] = src[(long)(r0 + ty*4 + i) * C + c0 + tx];
    __syncthreads();
    #pragma unroll
    for (int i = 0; i < 4; i++)
        dst[(long)(c0 + ty*4 + i) * R + r0 + tx] = __float2half_rn(tile[tx][ty*4 + i]);
}

__global__ void f2h_k(const float* __restrict__ src, half* __restrict__ dst)
{
    long i = ((long)blockIdx.x * 256 + threadIdx.x) * 8;
    float4 a = *(const float4*)(src + i);
    float4 b = *(const float4*)(src + i + 4);
    uint2 pa = pack4h(a), pb = pack4h(b);
    *(uint4*)(dst + i) = make_uint4(pa.x, pa.y, pb.x, pb.y);
}

// ---------------------------------------------------------------------------
// qkv GEMM, one head per CTA (BM=64), 128 threads, 4 warps of 64x32.
// cp.async 2-stage pipeline. A = WqT [512][3072], B = xh [b][512][2048].
// grid (16, 48, 2). blockIdx.y: type = y>>4, head = y&15.
// ---------------------------------------------------------------------------
constexpr int QLDA = 72, QLDB = 136, QEPILD = 132;
constexpr int QKV_SMEM = 64 * QEPILD * 4;      // 33,792 B (covers GEMM bufs 26,624)

__global__ void __launch_bounds__(128, 4)
qkv_gemm(const half* __restrict__ WqT, const half* __restrict__ xh,
         const float* __restrict__ q_scale, const float* __restrict__ k_scale,
         half* __restrict__ qh, half* __restrict__ kh, half* __restrict__ vh)
{
    extern __shared__ char smc[];
    half*  As = (half*)smc;                    // [2][32*72]   = 9216 B
    half*  Bs = (half*)(smc + 9216);           // [2][32*136]  = 17408 B
    float* Cs = (float*)smc;                   // 64 x 132 epilogue alias

    const int tid = threadIdx.x, wid = tid >> 5;
    const int m0 = blockIdx.y * 64, n0 = blockIdx.x * 128, b = blockIdx.z;
    const int wn = wid * 32;
    const half* B = xh + (long)b * Cc * Nn;
    const unsigned int asb = (unsigned int)__cvta_generic_to_shared(As);
    const unsigned int bsb = (unsigned int)__cvta_generic_to_shared(Bs);

    wmma::fragment<wmma::accumulator,16,16,16,float> acc[4][2];
    #pragma unroll
    for (int i = 0; i < 4; i++)
        #pragma unroll
        for (int j = 0; j < 2; j++) wmma::fill_fragment(acc[i][j], 0.f);

    auto ldgsts = [&](int k0, int buf) {
        #pragma unroll
        for (int g = 0; g < 2; g++) {          // A: 64x32 = 256 uint4
            int idx = tid + g*128, kk = idx >> 3, mq = idx & 7;
            cp16(asb + (buf*32*QLDA + kk*QLDA + mq*8)*2,
                 WqT + (long)(k0+kk)*(3*HDIM) + m0 + mq*8);
        }
        #pragma unroll
        for (int g = 0; g < 4; g++) {          // B: 32x128 = 512 uint4
            int idx = tid + g*128, kk = idx >> 4, nq = idx & 15;
            cp16(bsb + (buf*32*QLDB + kk*QLDB + nq*8)*2,
                 B + (long)(k0+kk)*Nn + n0 + nq*8);
        }
        asm volatile("cp.async.commit_group;" ::: "memory");
    };

    ldgsts(0, 0);

    #pragma unroll 1
    for (int it = 0; it < 16; it++) {
        const int cur = it & 1;
        if (it + 1 < 16) {
            ldgsts((it + 1) * 32, cur ^ 1);
            asm volatile("cp.async.wait_group 1;" ::: "memory");
        } else {
            asm volatile("cp.async.wait_group 0;" ::: "memory");
        }
        __syncthreads();

        #pragma unroll
        for (int kc = 0; kc < 32; kc += 16) {
            wmma::fragment<wmma::matrix_a,16,16,16,half,wmma::col_major> af[4];
            #pragma unroll
            for (int i = 0; i < 4; i++)
                wmma::load_matrix_sync(af[i], &As[cur*32*QLDA + kc*QLDA + i*16], QLDA);
            #pragma unroll
            for (int j = 0; j < 2; j++) {
                wmma::fragment<wmma::matrix_b,16,16,16,half,wmma::row_major> bf;
                wmma::load_matrix_sync(bf, &Bs[cur*32*QLDB + kc*QLDB + wn + j*16], QLDB);
                #pragma unroll
                for (int i = 0; i < 4; i++)
                    wmma::mma_sync(acc[i][j], af[i], bf, acc[i][j]);
            }
        }
        __syncthreads();   // buf cur consumed before it+2 overwrites it
    }

    // ---- epilogue: 64x128 fp32 tile -> smem -> norm/convert -> fp16 ----
    #pragma unroll
    for (int i = 0; i < 4; i++)
        #pragma unroll
        for (int j = 0; j < 2; j++)
            wmma::store_matrix_sync(Cs + (i*16)*QEPILD + wn + j*16,
                                    acc[i][j], QEPILD, wmma::mem_row_major);
    __syncthreads();

    {
        const int type = blockIdx.y >> 4;      // 0=q, 1=k, 2=v
        const int h    = blockIdx.y & 15;
        const int j    = tid;                  // one column per thread
        half* dst = (type == 0 ? qh : (type == 1 ? kh : vh))
                    + ((long)(b*HEADS + h) * DHEAD) * Nn + n0 + j;
        if (type == 2) {
            #pragma unroll
            for (int d = 0; d < DHEAD; d++)
                dst[(long)d*Nn] = __float2half_rn(Cs[d*QEPILD + j]);
        } else {
            float ss = 0.f;
            #pragma unroll
            for (int d = 0; d < DHEAD; d++) {
                float t = Cs[d*QEPILD + j];
                ss += t * t;
            }
            float inv = (type ? 1.0f : 8.0f) / fmaxf(sqrtf(ss), 1e-12f);
            const float* sc = type ? k_scale : q_scale;
            #pragma unroll
            for (int d = 0; d < DHEAD; d++)
                dst[(long)d*Nn] = __float2half_rn(Cs[d*QEPILD + j] * inv * sc[d]);
        }
    }
}

// ---------------------------------------------------------------------------
// out GEMM: 128 threads, 4 warps of 64x32, cp.async 2-stage, bias in accum.
// A = WoT [1024][512] half, B = aoh. grid (16, 8, 2).
// ---------------------------------------------------------------------------
constexpr int OLDA = 72, OLDB = 136;

__global__ void __launch_bounds__(128, 4)
out_gemm(const half* __restrict__ WoT, const half* __restrict__ Bg,
         float* __restrict__ Cg, const float* __restrict__ bias)
{
    __shared__ half As[2][32 * OLDA];
    __shared__ half Bs[2][32 * OLDB];

    const half* B = Bg + (long)blockIdx.z * HDIM * Nn;
    float*      C = Cg + (long)blockIdx.z * Cc * Nn;
    const int tid = threadIdx.x, wid = tid >> 5;
    const int m0 = blockIdx.y * 64, n0 = blockIdx.x * 128;
    const int wn = wid * 32;
    const unsigned int asb = (unsigned int)__cvta_generic_to_shared(&As[0][0]);
    const unsigned int bsb = (unsigned int)__cvta_generic_to_shared(&Bs[0][0]);

    wmma::fragment<wmma::accumulator,16,16,16,float> acc[4][2];
    {
        float* biasS = (float*)&As[0][0];       // 64 x 20 floats = 5120 B
        for (int l = tid; l < 64*20; l += 128)
            biasS[l] = bias[m0 + l/20];
        __syncthreads();
        #pragma unroll
        for (int i = 0; i < 4; i++)
            #pragma unroll
            for (int j = 0; j < 2; j++)
                wmma::load_matrix_sync(acc[i][j], biasS + (i*16)*20, 20,
                                       wmma::mem_row_major);
        __syncthreads();
    }

    auto ldgsts = [&](int k0, int buf) {
        #pragma unroll
        for (int g = 0; g < 2; g++) {
            int idx = tid + g*128, kk = idx >> 3, mq = idx & 7;
            cp16(asb + (buf*32*OLDA + kk*OLDA + mq*8)*2,
                 WoT + (long)(k0+kk)*Cc + m0 + mq*8);
        }
        #pragma unroll
        for (int g = 0; g < 4; g++) {
            int idx = tid + g*128, kk = idx >> 4, nq = idx & 15;
            cp16(bsb + (buf*32*OLDB + kk*OLDB + nq*8)*2,
                 B + (long)(k0+kk)*Nn + n0 + nq*8);
        }
        asm volatile("cp.async.commit_group;" ::: "memory");
    };

    ldgsts(0, 0);

    #pragma unroll 1
    for (int it = 0; it < 32; it++) {
        const int cur = it & 1;
        if (it + 1 < 32) {
            ldgsts((it + 1) * 32, cur ^ 1);
            asm volatile("cp.async.wait_group 1;" ::: "memory");
        } else {
            asm volatile("cp.async.wait_group 0;" ::: "memory");
        }
        __syncthreads();

        #pragma unroll
        for (int kc = 0; kc < 32; kc += 16) {
            wmma::fragment<wmma::matrix_a,16,16,16,half,wmma::col_major> af[4];
            #pragma unroll
            for (int i = 0; i < 4; i++)
                wmma::load_matrix_sync(af[i], &As[cur][kc*OLDA + i*16], OLDA);
            #pragma unroll
            for (int j = 0; j < 2; j++) {
                wmma::fragment<wmma::matrix_b,16,16,16,half,wmma::row_major> bf;
                wmma::load_matrix_sync(bf, &Bs[cur][kc*OLDB + wn + j*16], OLDB);
                #pragma unroll
                for (int i = 0; i < 4; i++)
                    wmma::mma_sync(acc[i][j], af[i], bf, acc[i][j]);
            }
        }
        __syncthreads();
    }

    #pragma unroll
    for (int i = 0; i < 4; i++)
        #pragma unroll
        for (int j = 0; j < 2; j++)
            wmma::store_matrix_sync(C + (long)(m0+i*16)*Nn + n0 + wn + j*16,
                                    acc[i][j], Nn, wmma::mem_row_major);
}

// ---------------------------------------------------------------------------
// Flash attention (unchanged from R11): fp16 WMMA, 2x2 warp split, 3 CTA/SM.
// ---------------------------------------------------------------------------
constexpr int FLH  = 136;
constexpr int QLH  = 72;
constexpr int SLDf = 68;
constexpr int PLH  = 136;
constexpr int KS_B = 0;
constexpr int VS_B = 17408;
constexpr int SF_B = 34816;
constexpr int RS_B = 69632;
constexpr int FLASH_SMEM = 70144;

__global__ void __launch_bounds__(128, 3)
flash_h(const half* __restrict__ qhg, const half* __restrict__ khg,
        const half* __restrict__ vhg, half* __restrict__ aoh)
{
    extern __shared__ char smc[];
    half*  Ks = (half*)(smc + KS_B);
    half*  Vs = (half*)(smc + VS_B);
    float* Sf = (float*)(smc + SF_B);
    float* rs = (float*)(smc + RS_B);
    half*  Qst = (half*)(smc + SF_B);

    const int tid = threadIdx.x, wid = tid >> 5, lane = tid & 31;
    const int r = wid >> 1, c = wid & 1;
    const int qi0 = blockIdx.x * 64;
    const int bh = blockIdx.y;
    const int b = bh >> 4, h = bh & 15;

    const half* qg = qhg + (long)bh * DHEAD * Nn;
    const half* kg = khg + (long)bh * DHEAD * Nn;
    const half* vg = vhg + (long)bh * DHEAD * Nn;
    const unsigned int ksb = (unsigned int)__cvta_generic_to_shared(Ks);
    const unsigned int vsb = (unsigned int)__cvta_generic_to_shared(Vs);

    for (int l = tid; l < 64*8; l += 128) {
        int d = l >> 3, i8 = (l & 7) * 8;
        *(uint4*)&Qst[d*QLH + i8] = *(const uint4*)(qg + (long)d*Nn + qi0 + i8);
    }
    __syncthreads();

    wmma::fragment<wmma::matrix_a,16,16,16,half,wmma::col_major> qf[2][4];
    #pragma unroll
    for (int m = 0; m < 2; m++)
        #pragma unroll
        for (int kc = 0; kc < 4; kc++)
            wmma::load_matrix_sync(qf[m][kc], Qst + kc*16*QLH + r*32 + m*16, QLH);

    wmma::fragment<wmma::accumulator,16,16,16,float> of[2][4];
    #pragma unroll
    for (int m = 0; m < 2; m++)
        #pragma unroll
        for (int dt = 0; dt < 4; dt++) wmma::fill_fragment(of[m][dt], 0.f);

    float rowsum = 0.f;
    float* Sw  = Sf + wid * (32*SLDf);
    half*  Phw = (half*)Sw;
    __syncthreads();

    for (int kt = 0; kt < Nn; kt += 128) {
        #pragma unroll
        for (int g = 0; g < 8; g++) {
            int l = tid + g*128;
            int d = l >> 4, j8 = (l & 15) * 8;
            cp16(ksb + (d*FLH + j8)*2, kg + (long)d*Nn + kt + j8);
            cp16(vsb + (d*FLH + j8)*2, vg + (long)d*Nn + kt + j8);
        }
        asm volatile("cp.async.commit_group;" ::: "memory");
        asm volatile("cp.async.wait_group 0;" ::: "memory");
        __syncthreads();

        #pragma unroll
        for (int jg = 0; jg < 2; jg++) {
            wmma::fragment<wmma::accumulator,16,16,16,float> sf[2][2];
            #pragma unroll
            for (int m = 0; m < 2; m++)
                #pragma unroll
                for (int jj = 0; jj < 2; jj++) wmma::fill_fragment(sf[m][jj], 0.f);
            #pragma unroll
            for (int kc = 0; kc < 4; kc++) {
                #pragma unroll
                for (int jj = 0; jj < 2; jj++) {
                    wmma::fragment<wmma::matrix_b,16,16,16,half,wmma::row_major> bf;
                    wmma::load_matrix_sync(bf, Ks + kc*16*FLH + c*64 + (jg*2+jj)*16, FLH);
                    wmma::mma_sync(sf[0][jj], qf[0][kc], bf, sf[0][jj]);
                    wmma::mma_sync(sf[1][jj], qf[1][kc], bf, sf[1][jj]);
                }
            }
            #pragma unroll
            for (int m = 0; m < 2; m++)
                #pragma unroll
                for (int jj = 0; jj < 2; jj++)
                    wmma::store_matrix_sync(Sw + m*16*SLDf + (jg*2+jj)*16,
                                            sf[m][jj], SLDf, wmma::mem_row_major);
        }
        __syncwarp();

        {
            float* prow = Sw + lane*SLDf;
            half*  drow = (half*)prow;
            float s = 0.f;
            {
                float4 t[8];
                #pragma unroll
                for (int g = 0; g < 8; g++) {
                    float4 v = ((const float4*)prow)[g];
                    v.x = __expf(v.x); v.y = __expf(v.y);
                    v.z = __expf(v.z); v.w = __expf(v.w);
                    s += v.x + v.y + v.z + v.w;
                    t[g] = v;
                }
                #pragma unroll
                for (int g = 0; g < 4; g++) {
                    uint2 a = pack4h(t[2*g]), bq = pack4h(t[2*g+1]);
                    ((uint4*)drow)[g] = make_uint4(a.x, a.y, bq.x, bq.y);
                }
            }
            {
                float4 t[8];
                #pragma unroll
                for (int g = 0; g < 8; g++) {
                    float4 v = ((const float4*)prow)[8+g];
                    v.x = __expf(v.x); v.y = __expf(v.y);
                    v.z = __expf(v.z); v.w = __expf(v.w);
                    s += v.x + v.y + v.z + v.w;
                    t[g] = v;
                }
                #pragma unroll
                for (int g = 0; g < 4; g++) {
                    uint2 a = pack4h(t[2*g]), bq = pack4h(t[2*g+1]);
                    ((uint4*)drow)[4+g] = make_uint4(a.x, a.y, bq.x, bq.y);
                }
            }
            rowsum += s;
        }
        __syncwarp();

        #pragma unroll
        for (int kc = 0; kc < 4; kc++) {
            wmma::fragment<wmma::matrix_a,16,16,16,half,wmma::row_major> af[2];
            #pragma unroll
            for (int m = 0; m < 2; m++)
                wmma::load_matrix_sync(af[m], Phw + m*16*PLH + kc*16, PLH);
            #pragma unroll
            for (int dt = 0; dt < 4; dt++) {
                wmma::fragment<wmma::matrix_b,16,16,16,half,wmma::col_major> bf;
                wmma::load_matrix_sync(bf, Vs + dt*16*FLH + c*64 + kc*16, FLH);
                wmma::mma_sync(of[0][dt], af[0], bf, of[0][dt]);
                wmma::mma_sync(of[1][dt], af[1], bf, of[1][dt]);
            }
        }
        __syncthreads();
    }

    #pragma unroll
    for (int m = 0; m < 2; m++)
        #pragma unroll
        for (int dt = 0; dt < 4; dt++)
            wmma::store_matrix_sync(Sw + m*16*SLDf + dt*16, of[m][dt], SLDf,
                                    wmma::mem_row_major);
    rs[wid*32 + lane] = rowsum;
    __syncthreads();

    {
        const int i = tid & 63, db = (tid >> 6) * 32;
        const int wA = (i >> 5) * 2, il = i & 31;
        float inv = 1.0f / (rs[wA*32 + il] + rs[(wA+1)*32 + il]);
        const float* SA = Sf + wA*(32*SLDf) + il*SLDf;
        const float* SB = SA + 32*SLDf;
        half* aog = aoh + ((long)b*HDIM + h*DHEAD)*Nn + qi0 + i;
        #pragma unroll
        for (int d = 0; d < 32; d++) {
            int dd = db + d;
            aog[(long)dd*Nn] = __float2half_rn((SA[dd] + SB[dd]) * inv);
        }
    }
}

// ---------------------------------------------------------------------------
extern "C" void kernel_launch(void* const* d_in, const int* in_sizes, int n_in,
                              void* d_out, int out_size)
{
    (void)in_sizes; (void)n_in; (void)out_size;
    const float* x       = (const float*)d_in[0];
    const float* Wqkv    = (const float*)d_in[1];
    const float* q_scale = (const float*)d_in[2];
    const float* k_scale = (const float*)d_in[3];
    const float* Wout    = (const float*)d_in[4];
    const float* bout    = (const float*)d_in[5];
    float* out = (float*)d_out;

    half *WqT, *WoT, *xh, *qh, *kh, *vh, *aoh;
    cudaGetSymbolAddress((void**)&WqT, g_WqT);
    cudaGetSymbolAddress((void**)&WoT, g_WoT);
    cudaGetSymbolAddress((void**)&xh,  g_xh);
    cudaGetSymbolAddress((void**)&qh,  g_qh);
    cudaGetSymbolAddress((void**)&kh,  g_kh);
    cudaGetSymbolAddress((void**)&vh,  g_vh);
    cudaGetSymbolAddress((void**)&aoh, g_aoh);

    cudaFuncSetAttribute(flash_h, cudaFuncAttributeMaxDynamicSharedMemorySize,
                         FLASH_SMEM);

    // 0) one-time transposed fp16 weights + x convert
    t_f2h<3*HDIM, Cc><<<dim3(Cc/32, 3*HDIM/32), dim3(32,8)>>>(Wqkv, WqT);
    t_f2h<Cc, HDIM><<<dim3(HDIM/32, Cc/32), dim3(32,8)>>>(Wout, WoT);
    f2h_k<<<(int)(((long)Bb*Cc*Nn)/2048), 256>>>(x, xh);

    // 1) qkv gemm + fused norm/scale/v-convert -> qh, kh, vh (fp16)
    qkv_gemm<<<dim3(Nn/128, 48, Bb), 128, QKV_SMEM>>>(
        WqT, xh, q_scale, k_scale, qh, kh, vh);

    // 2) flash attention -> aoh (fp16, channel-major)
    flash_h<<<dim3(Nn/64, BH), 128, FLASH_SMEM>>>(qh, kh, vh, aoh);

    // 3) out = WoT^T @ aoh + bout
    out_gemm<<<dim3(Nn/128, Cc/64, Bb), 128>>>(WoT, aoh, out, bout);
}

// round 13
// speedup vs baseline: 3.7341x; 1.0263x over previous
#include <cuda_runtime.h>
#include <cuda_fp16.h>
#include <mma.h>
#include <cstdint>

using namespace nvcuda;

// ---------------------------------------------------------------------------
// Attention_50921132261730 — R13: deeper async pipelines everywhere
//   t_f2h: Wqkv -> WqT fp16, Wout -> WoT fp16 (once)
//   qkv_gemm: 128 thr, warp 64x32, 3-stage cp.async, fused norm epilogue
//   flash: fp16 WMMA 2x2 split, double-buffered K/V, 1 barrier/iter, 2 CTA/SM
//   out_gemm: 128 thr, warp 64x32, 3-stage cp.async, bias in accumulator
// ---------------------------------------------------------------------------

constexpr int Bb = 2, Cc = 512, Nn = 2048, HEADS = 16, DHEAD = 64;
constexpr int HDIM = HEADS * DHEAD;    // 1024
constexpr int BH = Bb * HEADS;         // 32

__device__ half g_WqT[Cc * 3 * HDIM];          // [512][3072]
__device__ half g_WoT[HDIM * Cc];              // [1024][512]
__device__ half g_xh [(long)Bb * Cc * Nn];
__device__ half g_qh [(long)BH * DHEAD * Nn];
__device__ half g_kh [(long)BH * DHEAD * Nn];
__device__ half g_vh [(long)BH * DHEAD * Nn];
__device__ half g_aoh[(long)Bb * HDIM * Nn];

__device__ __forceinline__ uint2 pack4h(float4 v) {
    half2 a = __floats2half2_rn(v.x, v.y);
    half2 b = __floats2half2_rn(v.z, v.w);
    uint2 r;
    r.x = *reinterpret_cast<unsigned*>(&a);
    r.y = *reinterpret_cast<unsigned*>(&b);
    return r;
}
__device__ __forceinline__ void cp16(unsigned int s, const void* g) {
    asm volatile("cp.async.cg.shared.global [%0], [%1], 16;" :: "r"(s), "l"(g));
}

// ---------------------------------------------------------------------------
template<int R, int C>
__global__ void t_f2h(const float* __restrict__ src, half* __restrict__ dst)
{
    __shared__ float tile[32][33];
    const int c0 = blockIdx.x * 32, r0 = blockIdx.y * 32;
    const int tx = threadIdx.x, ty = threadIdx.y;
    #pragma unroll
    for (int i = 0; i < 4; i++)
        tile[ty*4 + i][tx] = src[(long)(r0 + ty*4 + i) * C + c0 + tx];
    __syncthreads();
    #pragma unroll
    for (int i = 0; i < 4; i++)
        dst[(long)(c0 + ty*4 + i) * R + r0 + tx] = __float2half_rn(tile[tx][ty*4 + i]);
}

__global__ void f2h_k(const float* __restrict__ src, half* __restrict__ dst)
{
    long i = ((long)blockIdx.x * 256 + threadIdx.x) * 8;
    float4 a = *(const float4*)(src + i);
    float4 b = *(const float4*)(src + i + 4);
    uint2 pa = pack4h(a), pb = pack4h(b);
    *(uint4*)(dst + i) = make_uint4(pa.x, pa.y, pb.x, pb.y);
}

// ---------------------------------------------------------------------------
// qkv GEMM: one head/CTA (BM=64), 128 thr, 4 warps of 64x32, 3-stage pipeline.
// A = WqT [512][3072], B = xh [b][512][2048]. grid (16, 48, 2).
// ---------------------------------------------------------------------------
constexpr int QLDA = 72, QLDB = 136, QEPILD = 132;
constexpr int QSTG_A = 32 * QLDA;     // halfs per A stage
constexpr int QSTG_B = 32 * QLDB;
constexpr int QKV_SMEM = 3 * (QSTG_A + QSTG_B) * 2 > 64 * QEPILD * 4
                       ? 3 * (QSTG_A + QSTG_B) * 2 : 64 * QEPILD * 4;  // 39,936

__global__ void __launch_bounds__(128, 4)
qkv_gemm(const half* __restrict__ WqT, const half* __restrict__ xh,
         const float* __restrict__ q_scale, const float* __restrict__ k_scale,
         half* __restrict__ qh, half* __restrict__ kh, half* __restrict__ vh)
{
    extern __shared__ char smc[];
    half*  As = (half*)smc;                    // [3][32*72]
    half*  Bs = As + 3 * QSTG_A;               // [3][32*136]
    float* Cs = (float*)smc;                   // 64 x 132 epilogue alias

    const int tid = threadIdx.x, wid = tid >> 5;
    const int m0 = blockIdx.y * 64, n0 = blockIdx.x * 128, b = blockIdx.z;
    const int wn = wid * 32;
    const half* B = xh + (long)b * Cc * Nn;
    const unsigned int asb = (unsigned int)__cvta_generic_to_shared(As);
    const unsigned int bsb = (unsigned int)__cvta_generic_to_shared(Bs);

    wmma::fragment<wmma::accumulator,16,16,16,float> acc[4][2];
    #pragma unroll
    for (int i = 0; i < 4; i++)
        #pragma unroll
        for (int j = 0; j < 2; j++) wmma::fill_fragment(acc[i][j], 0.f);

    auto ldgsts = [&](int k0, int buf) {
        #pragma unroll
        for (int g = 0; g < 2; g++) {          // A: 64x32 = 256 uint4
            int idx = tid + g*128, kk = idx >> 3, mq = idx & 7;
            cp16(asb + (buf*QSTG_A + kk*QLDA + mq*8)*2,
                 WqT + (long)(k0+kk)*(3*HDIM) + m0 + mq*8);
        }
        #pragma unroll
        for (int g = 0; g < 4; g++) {          // B: 32x128 = 512 uint4
            int idx = tid + g*128, kk = idx >> 4, nq = idx & 15;
            cp16(bsb + (buf*QSTG_B + kk*QLDB + nq*8)*2,
                 B + (long)(k0+kk)*Nn + n0 + nq*8);
        }
        asm volatile("cp.async.commit_group;" ::: "memory");
    };

    ldgsts(0, 0);
    ldgsts(32, 1);

    #pragma unroll 1
    for (int it = 0; it < 16; it++) {
        const int cur = it % 3;
        asm volatile("cp.async.wait_group 1;" ::: "memory");
        __syncthreads();
        if (it + 2 < 16) ldgsts((it + 2) * 32, (it + 2) % 3);

        #pragma unroll
        for (int kc = 0; kc < 32; kc += 16) {
            wmma::fragment<wmma::matrix_a,16,16,16,half,wmma::col_major> af[4];
            #pragma unroll
            for (int i = 0; i < 4; i++)
                wmma::load_matrix_sync(af[i], &As[cur*QSTG_A + kc*QLDA + i*16], QLDA);
            #pragma unroll
            for (int j = 0; j < 2; j++) {
                wmma::fragment<wmma::matrix_b,16,16,16,half,wmma::row_major> bf;
                wmma::load_matrix_sync(bf, &Bs[cur*QSTG_B + kc*QLDB + wn + j*16], QLDB);
                #pragma unroll
                for (int i = 0; i < 4; i++)
                    wmma::mma_sync(acc[i][j], af[i], bf, acc[i][j]);
            }
        }
    }
    __syncthreads();

    // ---- epilogue: 64x128 fp32 tile -> smem -> norm/convert -> fp16 ----
    #pragma unroll
    for (int i = 0; i < 4; i++)
        #pragma unroll
        for (int j = 0; j < 2; j++)
            wmma::store_matrix_sync(Cs + (i*16)*QEPILD + wn + j*16,
                                    acc[i][j], QEPILD, wmma::mem_row_major);
    __syncthreads();

    {
        const int type = blockIdx.y >> 4;      // 0=q, 1=k, 2=v
        const int h    = blockIdx.y & 15;
        const int j    = tid;                  // one column per thread
        half* dst = (type == 0 ? qh : (type == 1 ? kh : vh))
                    + ((long)(b*HEADS + h) * DHEAD) * Nn + n0 + j;
        if (type == 2) {
            #pragma unroll
            for (int d = 0; d < DHEAD; d++)
                dst[(long)d*Nn] = __float2half_rn(Cs[d*QEPILD + j]);
        } else {
            float ss = 0.f;
            #pragma unroll
            for (int d = 0; d < DHEAD; d++) {
                float t = Cs[d*QEPILD + j];
                ss += t * t;
            }
            float inv = (type ? 1.0f : 8.0f) / fmaxf(sqrtf(ss), 1e-12f);
            const float* sc = type ? k_scale : q_scale;
            #pragma unroll
            for (int d = 0; d < DHEAD; d++)
                dst[(long)d*Nn] = __float2half_rn(Cs[d*QEPILD + j] * inv * sc[d]);
        }
    }
}

// ---------------------------------------------------------------------------
// out GEMM: 128 thr, warp 64x32, 3-stage cp.async, bias in accumulator init.
// A = WoT [1024][512], B = aoh. grid (16, 8, 2).
// ---------------------------------------------------------------------------
constexpr int OLDA = 72, OLDB = 136;
constexpr int OSTG_A = 32 * OLDA;
constexpr int OSTG_B = 32 * OLDB;

__global__ void __launch_bounds__(128, 4)
out_gemm(const half* __restrict__ WoT, const half* __restrict__ Bg,
         float* __restrict__ Cg, const float* __restrict__ bias)
{
    __shared__ half As[3 * OSTG_A];
    __shared__ half Bs[3 * OSTG_B];

    const half* B = Bg + (long)blockIdx.z * HDIM * Nn;
    float*      C = Cg + (long)blockIdx.z * Cc * Nn;
    const int tid = threadIdx.x, wid = tid >> 5;
    const int m0 = blockIdx.y * 64, n0 = blockIdx.x * 128;
    const int wn = wid * 32;
    const unsigned int asb = (unsigned int)__cvta_generic_to_shared(As);
    const unsigned int bsb = (unsigned int)__cvta_generic_to_shared(Bs);

    wmma::fragment<wmma::accumulator,16,16,16,float> acc[4][2];
    {
        float* biasS = (float*)As;             // 64 x 20 floats = 5120 B
        for (int l = tid; l < 64*20; l += 128)
            biasS[l] = bias[m0 + l/20];
        __syncthreads();
        #pragma unroll
        for (int i = 0; i < 4; i++)
            #pragma unroll
            for (int j = 0; j < 2; j++)
                wmma::load_matrix_sync(acc[i][j], biasS + (i*16)*20, 20,
                                       wmma::mem_row_major);
        __syncthreads();
    }

    auto ldgsts = [&](int k0, int buf) {
        #pragma unroll
        for (int g = 0; g < 2; g++) {
            int idx = tid + g*128, kk = idx >> 3, mq = idx & 7;
            cp16(asb + (buf*OSTG_A + kk*OLDA + mq*8)*2,
                 WoT + (long)(k0+kk)*Cc + m0 + mq*8);
        }
        #pragma unroll
        for (int g = 0; g < 4; g++) {
            int idx = tid + g*128, kk = idx >> 4, nq = idx & 15;
            cp16(bsb + (buf*OSTG_B + kk*OLDB + nq*8)*2,
                 B + (long)(k0+kk)*Nn + n0 + nq*8);
        }
        asm volatile("cp.async.commit_group;" ::: "memory");
    };

    ldgsts(0, 0);
    ldgsts(32, 1);

    #pragma unroll 1
    for (int it = 0; it < 32; it++) {
        const int cur = it % 3;
        asm volatile("cp.async.wait_group 1;" ::: "memory");
        __syncthreads();
        if (it + 2 < 32) ldgsts((it + 2) * 32, (it + 2) % 3);

        #pragma unroll
        for (int kc = 0; kc < 32; kc += 16) {
            wmma::fragment<wmma::matrix_a,16,16,16,half,wmma::col_major> af[4];
            #pragma unroll
            for (int i = 0; i < 4; i++)
                wmma::load_matrix_sync(af[i], &As[cur*OSTG_A + kc*OLDA + i*16], OLDA);
            #pragma unroll
            for (int j = 0; j < 2; j++) {
                wmma::fragment<wmma::matrix_b,16,16,16,half,wmma::row_major> bf;
                wmma::load_matrix_sync(bf, &Bs[cur*OSTG_B + kc*OLDB + wn + j*16], OLDB);
                #pragma unroll
                for (int i = 0; i < 4; i++)
                    wmma::mma_sync(acc[i][j], af[i], bf, acc[i][j]);
            }
        }
    }

    #pragma unroll
    for (int i = 0; i < 4; i++)
        #pragma unroll
        for (int j = 0; j < 2; j++)
            wmma::store_matrix_sync(C + (long)(m0+i*16)*Nn + n0 + wn + j*16,
                                    acc[i][j], Nn, wmma::mem_row_major);
}

// ---------------------------------------------------------------------------
// Flash attention: fp16 WMMA, 2x2 warp split, DOUBLE-BUFFERED K/V,
// one __syncthreads per KV tile. 2 CTA/SM.
// ---------------------------------------------------------------------------
constexpr int FLH  = 136;
constexpr int QLH  = 72;
constexpr int SLDf = 68;
constexpr int PLH  = 136;
constexpr int KVSTG = 64 * FLH;                // halfs per K (or V) stage
constexpr int KS_B = 0;                        // K0,V0,K1,V1: 4*17408 = 69632
constexpr int SF_B = 4 * KVSTG * 2;            // 69632
constexpr int RS_B = SF_B + 4*32*SLDf*4;       // 69632 + 34816 = 104448
constexpr int FLASH_SMEM = RS_B + 512;         // 104,960

__global__ void __launch_bounds__(128, 2)
flash_h(const half* __restrict__ qhg, const half* __restrict__ khg,
        const half* __restrict__ vhg, half* __restrict__ aoh)
{
    extern __shared__ char smc[];
    half*  KV = (half*)(smc + KS_B);           // [2 stages][K 64xFLH | V 64xFLH]
    float* Sf = (float*)(smc + SF_B);
    float* rs = (float*)(smc + RS_B);
    half*  Qst = (half*)(smc + SF_B);

    const int tid = threadIdx.x, wid = tid >> 5, lane = tid & 31;
    const int r = wid >> 1, c = wid & 1;
    const int qi0 = blockIdx.x * 64;
    const int bh = blockIdx.y;
    const int b = bh >> 4, h = bh & 15;

    const half* qg = qhg + (long)bh * DHEAD * Nn;
    const half* kg = khg + (long)bh * DHEAD * Nn;
    const half* vg = vhg + (long)bh * DHEAD * Nn;
    const unsigned int kvb = (unsigned int)__cvta_generic_to_shared(KV);

    for (int l = tid; l < 64*8; l += 128) {
        int d = l >> 3, i8 = (l & 7) * 8;
        *(uint4*)&Qst[d*QLH + i8] = *(const uint4*)(qg + (long)d*Nn + qi0 + i8);
    }
    __syncthreads();

    wmma::fragment<wmma::matrix_a,16,16,16,half,wmma::col_major> qf[2][4];
    #pragma unroll
    for (int m = 0; m < 2; m++)
        #pragma unroll
        for (int kc = 0; kc < 4; kc++)
            wmma::load_matrix_sync(qf[m][kc], Qst + kc*16*QLH + r*32 + m*16, QLH);

    wmma::fragment<wmma::accumulator,16,16,16,float> of[2][4];
    #pragma unroll
    for (int m = 0; m < 2; m++)
        #pragma unroll
        for (int dt = 0; dt < 4; dt++) wmma::fill_fragment(of[m][dt], 0.f);

    float rowsum = 0.f;
    float* Sw  = Sf + wid * (32*SLDf);
    half*  Phw = (half*)Sw;
    __syncthreads();   // qf loads done before Sf reused as S

    auto ldkv = [&](int kt, int buf) {
        #pragma unroll
        for (int g = 0; g < 8; g++) {
            int l = tid + g*128;
            int d = l >> 4, j8 = (l & 15) * 8;
            cp16(kvb + (buf*2*KVSTG + d*FLH + j8)*2, kg + (long)d*Nn + kt + j8);
            cp16(kvb + (buf*2*KVSTG + KVSTG + d*FLH + j8)*2, vg + (long)d*Nn + kt + j8);
        }
        asm volatile("cp.async.commit_group;" ::: "memory");
    };

    ldkv(0, 0);

    #pragma unroll 1
    for (int t = 0; t < 16; t++) {
        const int cur = t & 1;
        half* Ks = KV + cur*2*KVSTG;
        half* Vs = Ks + KVSTG;

        asm volatile("cp.async.wait_group 0;" ::: "memory");
        __syncthreads();   // tile t ready; all warps done with buf cur (from t-2)
        if (t + 1 < 16) ldkv((t + 1) * 128, cur ^ 1);

        // ---- S = Q^T K : two j-groups ----
        #pragma unroll
        for (int jg = 0; jg < 2; jg++) {
            wmma::fragment<wmma::accumulator,16,16,16,float> sf[2][2];
            #pragma unroll
            for (int m = 0; m < 2; m++)
                #pragma unroll
                for (int jj = 0; jj < 2; jj++) wmma::fill_fragment(sf[m][jj], 0.f);
            #pragma unroll
            for (int kc = 0; kc < 4; kc++) {
                #pragma unroll
                for (int jj = 0; jj < 2; jj++) {
                    wmma::fragment<wmma::matrix_b,16,16,16,half,wmma::row_major> bf;
                    wmma::load_matrix_sync(bf, Ks + kc*16*FLH + c*64 + (jg*2+jj)*16, FLH);
                    wmma::mma_sync(sf[0][jj], qf[0][kc], bf, sf[0][jj]);
                    wmma::mma_sync(sf[1][jj], qf[1][kc], bf, sf[1][jj]);
                }
            }
            #pragma unroll
            for (int m = 0; m < 2; m++)
                #pragma unroll
                for (int jj = 0; jj < 2; jj++)
                    wmma::store_matrix_sync(Sw + m*16*SLDf + (jg*2+jj)*16,
                                            sf[m][jj], SLDf, wmma::mem_row_major);
        }
        __syncwarp();

        // ---- P = exp(S); per-thread rowsum; fp16 P over S rows ----
        {
            float* prow = Sw + lane*SLDf;
            half*  drow = (half*)prow;
            float s = 0.f;
            {
                float4 t4[8];
                #pragma unroll
                for (int g = 0; g < 8; g++) {
                    float4 v = ((const float4*)prow)[g];
                    v.x = __expf(v.x); v.y = __expf(v.y);
                    v.z = __expf(v.z); v.w = __expf(v.w);
                    s += v.x + v.y + v.z + v.w;
                    t4[g] = v;
                }
                #pragma unroll
                for (int g = 0; g < 4; g++) {
                    uint2 a = pack4h(t4[2*g]), bq = pack4h(t4[2*g+1]);
                    ((uint4*)drow)[g] = make_uint4(a.x, a.y, bq.x, bq.y);
                }
            }
            {
                float4 t4[8];
                #pragma unroll
                for (int g = 0; g < 8; g++) {
                    float4 v = ((const float4*)prow)[8+g];
                    v.x = __expf(v.x); v.y = __expf(v.y);
                    v.z = __expf(v.z); v.w = __expf(v.w);
                    s += v.x + v.y + v.z + v.w;
                    t4[g] = v;
                }
                #pragma unroll
                for (int g = 0; g < 4; g++) {
                    uint2 a = pack4h(t4[2*g]), bq = pack4h(t4[2*g+1]);
                    ((uint4*)drow)[4+g] = make_uint4(a.x, a.y, bq.x, bq.y);
                }
            }
            rowsum += s;
        }
        __syncwarp();

        // ---- O += P @ V^T over warp's 64-j slice ----
        #pragma unroll
        for (int kc = 0; kc < 4; kc++) {
            wmma::fragment<wmma::matrix_a,16,16,16,half,wmma::row_major> af[2];
            #pragma unroll
            for (int m = 0; m < 2; m++)
                wmma::load_matrix_sync(af[m], Phw + m*16*PLH + kc*16, PLH);
            #pragma unroll
            for (int dt = 0; dt < 4; dt++) {
                wmma::fragment<wmma::matrix_b,16,16,16,half,wmma::col_major> bf;
                wmma::load_matrix_sync(bf, Vs + dt*16*FLH + c*64 + kc*16, FLH);
                wmma::mma_sync(of[0][dt], af[0], bf, of[0][dt]);
                wmma::mma_sync(of[1][dt], af[1], bf, of[1][dt]);
            }
        }
    }

    __syncthreads();
    // ---- reduce O + rowsum across warp pair; write aoh fp16 ----
    #pragma unroll
    for (int m = 0; m < 2; m++)
        #pragma unroll
        for (int dt = 0; dt < 4; dt++)
            wmma::store_matrix_sync(Sw + m*16*SLDf + dt*16, of[m][dt], SLDf,
                                    wmma::mem_row_major);
    rs[wid*32 + lane] = rowsum;
    __syncthreads();

    {
        const int i = tid & 63, db = (tid >> 6) * 32;
        const int wA = (i >> 5) * 2, il = i & 31;
        float inv = 1.0f / (rs[wA*32 + il] + rs[(wA+1)*32 + il]);
        const float* SA = Sf + wA*(32*SLDf) + il*SLDf;
        const float* SB = SA + 32*SLDf;
        half* aog = aoh + ((long)b*HDIM + h*DHEAD)*Nn + qi0 + i;
        #pragma unroll
        for (int d = 0; d < 32; d++) {
            int dd = db + d;
            aog[(long)dd*Nn] = __float2half_rn((SA[dd] + SB[dd]) * inv);
        }
    }
}

// ---------------------------------------------------------------------------
extern "C" void kernel_launch(void* const* d_in, const int* in_sizes, int n_in,
                              void* d_out, int out_size)
{
    (void)in_sizes; (void)n_in; (void)out_size;
    const float* x       = (const float*)d_in[0];
    const float* Wqkv    = (const float*)d_in[1];
    const float* q_scale = (const float*)d_in[2];
    const float* k_scale = (const float*)d_in[3];
    const float* Wout    = (const float*)d_in[4];
    const float* bout    = (const float*)d_in[5];
    float* out = (float*)d_out;

    half *WqT, *WoT, *xh, *qh, *kh, *vh, *aoh;
    cudaGetSymbolAddress((void**)&WqT, g_WqT);
    cudaGetSymbolAddress((void**)&WoT, g_WoT);
    cudaGetSymbolAddress((void**)&xh,  g_xh);
    cudaGetSymbolAddress((void**)&qh,  g_qh);
    cudaGetSymbolAddress((void**)&kh,  g_kh);
    cudaGetSymbolAddress((void**)&vh,  g_vh);
    cudaGetSymbolAddress((void**)&aoh, g_aoh);

    cudaFuncSetAttribute(flash_h, cudaFuncAttributeMaxDynamicSharedMemorySize,
                         FLASH_SMEM);

    // 0) one-time transposed fp16 weights + x convert
    t_f2h<3*HDIM, Cc><<<dim3(Cc/32, 3*HDIM/32), dim3(32,8)>>>(Wqkv, WqT);
    t_f2h<Cc, HDIM><<<dim3(HDIM/32, Cc/32), dim3(32,8)>>>(Wout, WoT);
    f2h_k<<<(int)(((long)Bb*Cc*Nn)/2048), 256>>>(x, xh);

    // 1) qkv gemm + fused norm/scale/v-convert -> qh, kh, vh (fp16)
    qkv_gemm<<<dim3(Nn/128, 48, Bb), 128, QKV_SMEM>>>(
        WqT, xh, q_scale, k_scale, qh, kh, vh);

    // 2) flash attention -> aoh (fp16, channel-major)
    flash_h<<<dim3(Nn/64, BH), 128, FLASH_SMEM>>>(qh, kh, vh, aoh);

    // 3) out = WoT^T @ aoh + bout
    out_gemm<<<dim3(Nn/128, Cc/64, Bb), 128>>>(WoT, aoh, out, bout);
}

// round 14
// speedup vs baseline: 4.2879x; 1.1483x over previous
#include <cuda_runtime.h>
#include <cuda_fp16.h>
#include <mma.h>
#include <cstdint>

using namespace nvcuda;

// ---------------------------------------------------------------------------
// Attention_50921132261730 — R14: FA2-style register-resident flash (raw mma)
//   t_f2h: Wqkv -> WqT fp16, Wout -> WoT fp16 (once)
//   qkv_gemm: unchanged R13 (3-stage cp.async, fused norm epilogue)
//   flash: raw mma.sync.m16n8k16; S,P,O in registers; exp in-register;
//          ldmatrix K/V frags; cp.async double-buffered KV; 1 barrier/iter
//   out_gemm: unchanged R13
// ---------------------------------------------------------------------------

constexpr int Bb = 2, Cc = 512, Nn = 2048, HEADS = 16, DHEAD = 64;
constexpr int HDIM = HEADS * DHEAD;    // 1024
constexpr int BH = Bb * HEADS;         // 32

__device__ half g_WqT[Cc * 3 * HDIM];          // [512][3072]
__device__ half g_WoT[HDIM * Cc];              // [1024][512]
__device__ half g_xh [(long)Bb * Cc * Nn];
__device__ half g_qh [(long)BH * DHEAD * Nn];
__device__ half g_kh [(long)BH * DHEAD * Nn];
__device__ half g_vh [(long)BH * DHEAD * Nn];
__device__ half g_aoh[(long)Bb * HDIM * Nn];

__device__ __forceinline__ uint2 pack4h(float4 v) {
    half2 a = __floats2half2_rn(v.x, v.y);
    half2 b = __floats2half2_rn(v.z, v.w);
    uint2 r;
    r.x = *reinterpret_cast<unsigned*>(&a);
    r.y = *reinterpret_cast<unsigned*>(&b);
    return r;
}
__device__ __forceinline__ void cp16(unsigned int s, const void* g) {
    asm volatile("cp.async.cg.shared.global [%0], [%1], 16;" :: "r"(s), "l"(g));
}
__device__ __forceinline__ void ldsm_x4(uint32_t* r, unsigned int a) {
    asm volatile("ldmatrix.sync.aligned.m8n8.x4.shared.b16 {%0,%1,%2,%3}, [%4];"
                 : "=r"(r[0]), "=r"(r[1]), "=r"(r[2]), "=r"(r[3]) : "r"(a));
}
__device__ __forceinline__ void ldsm_x4t(uint32_t* r, unsigned int a) {
    asm volatile("ldmatrix.sync.aligned.m8n8.x4.trans.shared.b16 {%0,%1,%2,%3}, [%4];"
                 : "=r"(r[0]), "=r"(r[1]), "=r"(r[2]), "=r"(r[3]) : "r"(a));
}
__device__ __forceinline__ void mma16816(float* c, const uint32_t* a,
                                         uint32_t b0, uint32_t b1) {
    asm volatile("mma.sync.aligned.m16n8k16.row.col.f32.f16.f16.f32 "
                 "{%0,%1,%2,%3}, {%4,%5,%6,%7}, {%8,%9}, {%0,%1,%2,%3};"
                 : "+f"(c[0]), "+f"(c[1]), "+f"(c[2]), "+f"(c[3])
                 : "r"(a[0]), "r"(a[1]), "r"(a[2]), "r"(a[3]), "r"(b0), "r"(b1));
}

// ---------------------------------------------------------------------------
template<int R, int C>
__global__ void t_f2h(const float* __restrict__ src, half* __restrict__ dst)
{
    __shared__ float tile[32][33];
    const int c0 = blockIdx.x * 32, r0 = blockIdx.y * 32;
    const int tx = threadIdx.x, ty = threadIdx.y;
    #pragma unroll
    for (int i = 0; i < 4; i++)
        tile[ty*4 + i][tx] = src[(long)(r0 + ty*4 + i) * C + c0 + tx];
    __syncthreads();
    #pragma unroll
    for (int i = 0; i < 4; i++)
        dst[(long)(c0 + ty*4 + i) * R + r0 + tx] = __float2half_rn(tile[tx][ty*4 + i]);
}

__global__ void f2h_k(const float* __restrict__ src, half* __restrict__ dst)
{
    long i = ((long)blockIdx.x * 256 + threadIdx.x) * 8;
    float4 a = *(const float4*)(src + i);
    float4 b = *(const float4*)(src + i + 4);
    uint2 pa = pack4h(a), pb = pack4h(b);
    *(uint4*)(dst + i) = make_uint4(pa.x, pa.y, pb.x, pb.y);
}

// ---------------------------------------------------------------------------
// qkv GEMM (unchanged R13): one head/CTA, 128 thr, 3-stage cp.async pipeline.
// ---------------------------------------------------------------------------
constexpr int QLDA = 72, QLDB = 136, QEPILD = 132;
constexpr int QSTG_A = 32 * QLDA;
constexpr int QSTG_B = 32 * QLDB;
constexpr int QKV_SMEM = 3 * (QSTG_A + QSTG_B) * 2 > 64 * QEPILD * 4
                       ? 3 * (QSTG_A + QSTG_B) * 2 : 64 * QEPILD * 4;

__global__ void __launch_bounds__(128, 4)
qkv_gemm(const half* __restrict__ WqT, const half* __restrict__ xh,
         const float* __restrict__ q_scale, const float* __restrict__ k_scale,
         half* __restrict__ qh, half* __restrict__ kh, half* __restrict__ vh)
{
    extern __shared__ char smc[];
    half*  As = (half*)smc;
    half*  Bs = As + 3 * QSTG_A;
    float* Cs = (float*)smc;

    const int tid = threadIdx.x, wid = tid >> 5;
    const int m0 = blockIdx.y * 64, n0 = blockIdx.x * 128, b = blockIdx.z;
    const int wn = wid * 32;
    const half* B = xh + (long)b * Cc * Nn;
    const unsigned int asb = (unsigned int)__cvta_generic_to_shared(As);
    const unsigned int bsb = (unsigned int)__cvta_generic_to_shared(Bs);

    wmma::fragment<wmma::accumulator,16,16,16,float> acc[4][2];
    #pragma unroll
    for (int i = 0; i < 4; i++)
        #pragma unroll
        for (int j = 0; j < 2; j++) wmma::fill_fragment(acc[i][j], 0.f);

    auto ldgsts = [&](int k0, int buf) {
        #pragma unroll
        for (int g = 0; g < 2; g++) {
            int idx = tid + g*128, kk = idx >> 3, mq = idx & 7;
            cp16(asb + (buf*QSTG_A + kk*QLDA + mq*8)*2,
                 WqT + (long)(k0+kk)*(3*HDIM) + m0 + mq*8);
        }
        #pragma unroll
        for (int g = 0; g < 4; g++) {
            int idx = tid + g*128, kk = idx >> 4, nq = idx & 15;
            cp16(bsb + (buf*QSTG_B + kk*QLDB + nq*8)*2,
                 B + (long)(k0+kk)*Nn + n0 + nq*8);
        }
        asm volatile("cp.async.commit_group;" ::: "memory");
    };

    ldgsts(0, 0);
    ldgsts(32, 1);

    #pragma unroll 1
    for (int it = 0; it < 16; it++) {
        const int cur = it % 3;
        asm volatile("cp.async.wait_group 1;" ::: "memory");
        __syncthreads();
        if (it + 2 < 16) ldgsts((it + 2) * 32, (it + 2) % 3);

        #pragma unroll
        for (int kc = 0; kc < 32; kc += 16) {
            wmma::fragment<wmma::matrix_a,16,16,16,half,wmma::col_major> af[4];
            #pragma unroll
            for (int i = 0; i < 4; i++)
                wmma::load_matrix_sync(af[i], &As[cur*QSTG_A + kc*QLDA + i*16], QLDA);
            #pragma unroll
            for (int j = 0; j < 2; j++) {
                wmma::fragment<wmma::matrix_b,16,16,16,half,wmma::row_major> bf;
                wmma::load_matrix_sync(bf, &Bs[cur*QSTG_B + kc*QLDB + wn + j*16], QLDB);
                #pragma unroll
                for (int i = 0; i < 4; i++)
                    wmma::mma_sync(acc[i][j], af[i], bf, acc[i][j]);
            }
        }
    }
    __syncthreads();

    #pragma unroll
    for (int i = 0; i < 4; i++)
        #pragma unroll
        for (int j = 0; j < 2; j++)
            wmma::store_matrix_sync(Cs + (i*16)*QEPILD + wn + j*16,
                                    acc[i][j], QEPILD, wmma::mem_row_major);
    __syncthreads();

    {
        const int type = blockIdx.y >> 4;
        const int h    = blockIdx.y & 15;
        const int j    = tid;
        half* dst = (type == 0 ? qh : (type == 1 ? kh : vh))
                    + ((long)(b*HEADS + h) * DHEAD) * Nn + n0 + j;
        if (type == 2) {
            #pragma unroll
            for (int d = 0; d < DHEAD; d++)
                dst[(long)d*Nn] = __float2half_rn(Cs[d*QEPILD + j]);
        } else {
            float ss = 0.f;
            #pragma unroll
            for (int d = 0; d < DHEAD; d++) {
                float t = Cs[d*QEPILD + j];
                ss += t * t;
            }
            float inv = (type ? 1.0f : 8.0f) / fmaxf(sqrtf(ss), 1e-12f);
            const float* sc = type ? k_scale : q_scale;
            #pragma unroll
            for (int d = 0; d < DHEAD; d++)
                dst[(long)d*Nn] = __float2half_rn(Cs[d*QEPILD + j] * inv * sc[d]);
        }
    }
}

// ---------------------------------------------------------------------------
// out GEMM (unchanged R13)
// ---------------------------------------------------------------------------
constexpr int OLDA = 72, OLDB = 136;
constexpr int OSTG_A = 32 * OLDA;
constexpr int OSTG_B = 32 * OLDB;

__global__ void __launch_bounds__(128, 4)
out_gemm(const half* __restrict__ WoT, const half* __restrict__ Bg,
         float* __restrict__ Cg, const float* __restrict__ bias)
{
    __shared__ half As[3 * OSTG_A];
    __shared__ half Bs[3 * OSTG_B];

    const half* B = Bg + (long)blockIdx.z * HDIM * Nn;
    float*      C = Cg + (long)blockIdx.z * Cc * Nn;
    const int tid = threadIdx.x, wid = tid >> 5;
    const int m0 = blockIdx.y * 64, n0 = blockIdx.x * 128;
    const int wn = wid * 32;
    const unsigned int asb = (unsigned int)__cvta_generic_to_shared(As);
    const unsigned int bsb = (unsigned int)__cvta_generic_to_shared(Bs);

    wmma::fragment<wmma::accumulator,16,16,16,float> acc[4][2];
    {
        float* biasS = (float*)As;
        for (int l = tid; l < 64*20; l += 128)
            biasS[l] = bias[m0 + l/20];
        __syncthreads();
        #pragma unroll
        for (int i = 0; i < 4; i++)
            #pragma unroll
            for (int j = 0; j < 2; j++)
                wmma::load_matrix_sync(acc[i][j], biasS + (i*16)*20, 20,
                                       wmma::mem_row_major);
        __syncthreads();
    }

    auto ldgsts = [&](int k0, int buf) {
        #pragma unroll
        for (int g = 0; g < 2; g++) {
            int idx = tid + g*128, kk = idx >> 3, mq = idx & 7;
            cp16(asb + (buf*OSTG_A + kk*OLDA + mq*8)*2,
                 WoT + (long)(k0+kk)*Cc + m0 + mq*8);
        }
        #pragma unroll
        for (int g = 0; g < 4; g++) {
            int idx = tid + g*128, kk = idx >> 4, nq = idx & 15;
            cp16(bsb + (buf*OSTG_B + kk*OLDB + nq*8)*2,
                 B + (long)(k0+kk)*Nn + n0 + nq*8);
        }
        asm volatile("cp.async.commit_group;" ::: "memory");
    };

    ldgsts(0, 0);
    ldgsts(32, 1);

    #pragma unroll 1
    for (int it = 0; it < 32; it++) {
        const int cur = it % 3;
        asm volatile("cp.async.wait_group 1;" ::: "memory");
        __syncthreads();
        if (it + 2 < 32) ldgsts((it + 2) * 32, (it + 2) % 3);

        #pragma unroll
        for (int kc = 0; kc < 32; kc += 16) {
            wmma::fragment<wmma::matrix_a,16,16,16,half,wmma::col_major> af[4];
            #pragma unroll
            for (int i = 0; i < 4; i++)
                wmma::load_matrix_sync(af[i], &As[cur*OSTG_A + kc*OLDA + i*16], OLDA);
            #pragma unroll
            for (int j = 0; j < 2; j++) {
                wmma::fragment<wmma::matrix_b,16,16,16,half,wmma::row_major> bf;
                wmma::load_matrix_sync(bf, &Bs[cur*OSTG_B + kc*OLDB + wn + j*16], OLDB);
                #pragma unroll
                for (int i = 0; i < 4; i++)
                    wmma::mma_sync(acc[i][j], af[i], bf, acc[i][j]);
            }
        }
    }

    #pragma unroll
    for (int i = 0; i < 4; i++)
        #pragma unroll
        for (int j = 0; j < 2; j++)
            wmma::store_matrix_sync(C + (long)(m0+i*16)*Nn + n0 + wn + j*16,
                                    acc[i][j], Nn, wmma::mem_row_major);
}

// ---------------------------------------------------------------------------
// Flash attention — FA2-style, raw m16n8k16, register-resident S/P/O.
// 128 thr, 4 warps in 2x2: warp (r,c) owns rows r*32..+32, cols c*64..+64.
// KV double-buffered via cp.async. SMEM: KV 69632 + Sf 34816 + rs. 2 CTA/SM.
// ---------------------------------------------------------------------------
constexpr int FLH  = 136;
constexpr int QLH  = 72;
constexpr int SLDf = 68;
constexpr int KVSTG = 64 * FLH;
constexpr int SF_B = 4 * KVSTG * 2;            // 69632
constexpr int RS_B = SF_B + 4*32*SLDf*4;       // 104448
constexpr int FLASH_SMEM = RS_B + 512;         // 104,960

__global__ void __launch_bounds__(128)
flash_h(const half* __restrict__ qhg, const half* __restrict__ khg,
        const half* __restrict__ vhg, half* __restrict__ aoh)
{
    extern __shared__ char smc[];
    half*  KV = (half*)smc;
    float* Sf = (float*)(smc + SF_B);
    float* rs = (float*)(smc + RS_B);
    half*  Qst = (half*)(smc + SF_B);

    const int tid = threadIdx.x, wid = tid >> 5, lane = tid & 31;
    const int r = wid >> 1, c = wid & 1;
    const int qi0 = blockIdx.x * 64;
    const int bh = blockIdx.y;
    const int b = bh >> 4, h = bh & 15;

    const half* qg = qhg + (long)bh * DHEAD * Nn;
    const half* kg = khg + (long)bh * DHEAD * Nn;
    const half* vg = vhg + (long)bh * DHEAD * Nn;
    const unsigned int kvb = (unsigned int)__cvta_generic_to_shared(KV);
    const unsigned int qsb = (unsigned int)__cvta_generic_to_shared(Qst);

    // ---- Q stage (d,i) 64x64 half ----
    for (int l = tid; l < 64*8; l += 128) {
        int d = l >> 3, i8 = (l & 7) * 8;
        *(uint4*)&Qst[d*QLH + i8] = *(const uint4*)(qg + (long)d*Nn + qi0 + i8);
    }
    __syncthreads();

    // ---- Q A-frags: [mi][kc][4], ldmatrix.x4.trans from (d,i) ----
    uint32_t qa[2][4][4];
    #pragma unroll
    for (int mi = 0; mi < 2; mi++)
        #pragma unroll
        for (int kc = 0; kc < 4; kc++) {
            int row = kc*16 + (lane & 7) + ((lane >> 4) & 1) * 8;
            int col = r*32 + mi*16 + ((lane >> 3) & 1) * 8;
            ldsm_x4t(qa[mi][kc], qsb + (row*QLH + col) * 2);
        }

    float oc[2][8][4];
    #pragma unroll
    for (int mi = 0; mi < 2; mi++)
        #pragma unroll
        for (int dn = 0; dn < 8; dn++)
            #pragma unroll
            for (int q = 0; q < 4; q++) oc[mi][dn][q] = 0.f;
    float rsum[4] = {0.f, 0.f, 0.f, 0.f};
    __syncthreads();   // Qst (Sf alias) free

    auto ldkv = [&](int kt, int buf) {
        #pragma unroll
        for (int g = 0; g < 8; g++) {
            int l = tid + g*128;
            int d = l >> 4, j8 = (l & 15) * 8;
            cp16(kvb + (buf*2*KVSTG + d*FLH + j8)*2, kg + (long)d*Nn + kt + j8);
            cp16(kvb + (buf*2*KVSTG + KVSTG + d*FLH + j8)*2, vg + (long)d*Nn + kt + j8);
        }
        asm volatile("cp.async.commit_group;" ::: "memory");
    };

    ldkv(0, 0);
    const int jbase = c * 64;

    #pragma unroll 1
    for (int t = 0; t < 16; t++) {
        const int cur = t & 1;
        const unsigned int ksB = kvb + (cur*2*KVSTG) * 2;
        const unsigned int vsB = ksB + KVSTG * 2;

        asm volatile("cp.async.wait_group 0;" ::: "memory");
        __syncthreads();
        if (t + 1 < 16) ldkv((t + 1) * 128, cur ^ 1);

        // ---- S = Q K^T : sc[mi][nj][4] over warp's 32x64 slice ----
        float sc[2][8][4];
        #pragma unroll
        for (int mi = 0; mi < 2; mi++)
            #pragma unroll
            for (int nj = 0; nj < 8; nj++)
                #pragma unroll
                for (int q = 0; q < 4; q++) sc[mi][nj][q] = 0.f;

        #pragma unroll
        for (int kc = 0; kc < 4; kc++) {
            uint32_t kb[4][4];
            #pragma unroll
            for (int njp = 0; njp < 4; njp++) {
                int row = kc*16 + (lane & 7) + ((lane >> 3) & 1) * 8;
                int col = jbase + njp*16 + ((lane >> 4) & 1) * 8;
                ldsm_x4t(kb[njp], ksB + (row*FLH + col) * 2);
            }
            #pragma unroll
            for (int mi = 0; mi < 2; mi++)
                #pragma unroll
                for (int nj = 0; nj < 8; nj++)
                    mma16816(sc[mi][nj], qa[mi][kc],
                             kb[nj >> 1][(nj & 1) * 2], kb[nj >> 1][(nj & 1) * 2 + 1]);
        }

        // ---- P = exp(S) in-register (|S|<=8, no shift); pack A-frags ----
        uint32_t pa[2][4][4];
        #pragma unroll
        for (int mi = 0; mi < 2; mi++)
            #pragma unroll
            for (int nj = 0; nj < 8; nj++) {
                float e0 = __expf(sc[mi][nj][0]);
                float e1 = __expf(sc[mi][nj][1]);
                float e2 = __expf(sc[mi][nj][2]);
                float e3 = __expf(sc[mi][nj][3]);
                rsum[mi*2]   += e0 + e1;
                rsum[mi*2+1] += e2 + e3;
                half2 h01 = __floats2half2_rn(e0, e1);
                half2 h23 = __floats2half2_rn(e2, e3);
                int kj = nj >> 1, lo = (nj & 1) * 2;
                pa[mi][kj][lo]     = *reinterpret_cast<unsigned*>(&h01);
                pa[mi][kj][lo + 1] = *reinterpret_cast<unsigned*>(&h23);
            }

        // ---- O += P V^T : oc[mi][dn] over all 64 d ----
        #pragma unroll
        for (int kj = 0; kj < 4; kj++) {
            uint32_t vb[4][4];
            #pragma unroll
            for (int p = 0; p < 4; p++) {
                int row = p*16 + (lane & 7) + ((lane >> 4) & 1) * 8;
                int col = jbase + kj*16 + ((lane >> 3) & 1) * 8;
                ldsm_x4(vb[p], vsB + (row*FLH + col) * 2);
            }
            #pragma unroll
            for (int mi = 0; mi < 2; mi++)
                #pragma unroll
                for (int dn = 0; dn < 8; dn++)
                    mma16816(oc[mi][dn], pa[mi][kj],
                             vb[dn >> 1][(dn & 1) * 2], vb[dn >> 1][(dn & 1) * 2 + 1]);
        }
    }

    // ---- rowsum: reduce over 4 lanes sharing a row; write rs ----
    #pragma unroll
    for (int q = 0; q < 4; q++) {
        rsum[q] += __shfl_xor_sync(0xffffffffu, rsum[q], 1);
        rsum[q] += __shfl_xor_sync(0xffffffffu, rsum[q], 2);
    }
    if ((lane & 3) == 0) {
        int rr = lane >> 2;
        rs[wid*32 + rr]      = rsum[0];
        rs[wid*32 + rr + 8]  = rsum[1];
        rs[wid*32 + rr + 16] = rsum[2];
        rs[wid*32 + rr + 24] = rsum[3];
    }

    // ---- stage O partials to Sf (per-warp region) ----
    {
        float* Sw = Sf + wid * (32*SLDf);
        #pragma unroll
        for (int mi = 0; mi < 2; mi++)
            #pragma unroll
            for (int dn = 0; dn < 8; dn++) {
                int row = mi*16 + (lane >> 2);
                int colb = dn*8 + 2*(lane & 3);
                Sw[row*SLDf + colb]       = oc[mi][dn][0];
                Sw[row*SLDf + colb + 1]   = oc[mi][dn][1];
                Sw[(row+8)*SLDf + colb]     = oc[mi][dn][2];
                Sw[(row+8)*SLDf + colb + 1] = oc[mi][dn][3];
            }
    }
    __syncthreads();

    // ---- cross-pair reduce + normalize + write aoh fp16 ----
    {
        const int i = tid & 63, db = (tid >> 6) * 32;
        const int wA = (i >> 5) * 2, il = i & 31;
        float inv = 1.0f / (rs[wA*32 + il] + rs[(wA+1)*32 + il]);
        const float* SA = Sf + wA*(32*SLDf) + il*SLDf;
        const float* SB = SA + 32*SLDf;
        half* aog = aoh + ((long)b*HDIM + h*DHEAD)*Nn + qi0 + i;
        #pragma unroll
        for (int d = 0; d < 32; d++) {
            int dd = db + d;
            aog[(long)dd*Nn] = __float2half_rn((SA[dd] + SB[dd]) * inv);
        }
    }
}

// ---------------------------------------------------------------------------
extern "C" void kernel_launch(void* const* d_in, const int* in_sizes, int n_in,
                              void* d_out, int out_size)
{
    (void)in_sizes; (void)n_in; (void)out_size;
    const float* x       = (const float*)d_in[0];
    const float* Wqkv    = (const float*)d_in[1];
    const float* q_scale = (const float*)d_in[2];
    const float* k_scale = (const float*)d_in[3];
    const float* Wout    = (const float*)d_in[4];
    const float* bout    = (const float*)d_in[5];
    float* out = (float*)d_out;

    half *WqT, *WoT, *xh, *qh, *kh, *vh, *aoh;
    cudaGetSymbolAddress((void**)&WqT, g_WqT);
    cudaGetSymbolAddress((void**)&WoT, g_WoT);
    cudaGetSymbolAddress((void**)&xh,  g_xh);
    cudaGetSymbolAddress((void**)&qh,  g_qh);
    cudaGetSymbolAddress((void**)&kh,  g_kh);
    cudaGetSymbolAddress((void**)&vh,  g_vh);
    cudaGetSymbolAddress((void**)&aoh, g_aoh);

    cudaFuncSetAttribute(flash_h, cudaFuncAttributeMaxDynamicSharedMemorySize,
                         FLASH_SMEM);

    // 0) one-time transposed fp16 weights + x convert
    t_f2h<3*HDIM, Cc><<<dim3(Cc/32, 3*HDIM/32), dim3(32,8)>>>(Wqkv, WqT);
    t_f2h<Cc, HDIM><<<dim3(HDIM/32, Cc/32), dim3(32,8)>>>(Wout, WoT);
    f2h_k<<<(int)(((long)Bb*Cc*Nn)/2048), 256>>>(x, xh);

    // 1) qkv gemm + fused norm/scale/v-convert -> qh, kh, vh (fp16)
    qkv_gemm<<<dim3(Nn/128, 48, Bb), 128, QKV_SMEM>>>(
        WqT, xh, q_scale, k_scale, qh, kh, vh);

    // 2) flash attention -> aoh (fp16, channel-major)
    flash_h<<<dim3(Nn/64, BH), 128, FLASH_SMEM>>>(qh, kh, vh, aoh);

    // 3) out = WoT^T @ aoh + bout
    out_gemm<<<dim3(Nn/128, Cc/64, Bb), 128>>>(WoT, aoh, out, bout);
}